// round 6
// baseline (speedup 1.0000x reference)
#include <cuda_runtime.h>
#include <cuda_bf16.h>
#include <math.h>
#include <stdint.h>

#define BB 4
#define SS 4096
#define DD 256
#define MTOT (BB*SS)

// ---------------------------------------------------------------------------
// Scratch (allocation-free rule: device globals)
// ---------------------------------------------------------------------------
__device__ __align__(16) __nv_bfloat16 g_qh[MTOT*DD],  g_ql[MTOT*DD];
__device__ __align__(16) __nv_bfloat16 g_kh[MTOT*DD],  g_kl[MTOT*DD];
__device__ __align__(16) __nv_bfloat16 g_vh[MTOT*DD],  g_vl[MTOT*DD];
__device__ __align__(16) __nv_bfloat16 g_wqh[DD*DD], g_wql[DD*DD];
__device__ __align__(16) __nv_bfloat16 g_wkh[DD*DD], g_wkl[DD*DD];
__device__ __align__(16) __nv_bfloat16 g_wvh[DD*DD], g_wvl[DD*DD];
__device__ __align__(16) __nv_bfloat16 g_woh[DD*DD], g_wol[DD*DD];
__device__ __align__(16) __nv_bfloat16 g_qph[MTOT*DD], g_qpl[MTOT*DD];
__device__ __align__(16) __nv_bfloat16 g_kph[MTOT*DD], g_kpl[MTOT*DD];
__device__ float g_vp[MTOT*DD];
__device__ __align__(16) __nv_bfloat16 g_vth[MTOT*DD], g_vtl[MTOT*DD];  // Vp^T [b][d][s]
__device__ __align__(16) __nv_bfloat16 g_ah[(size_t)BB*SS*SS], g_al[(size_t)BB*SS*SS];
__device__ __align__(16) __nv_bfloat16 g_cth[MTOT*DD], g_ctl[MTOT*DD];

// ---------------------------------------------------------------------------
// Portable-PTX helpers (compute_103-safe)
// ---------------------------------------------------------------------------
__device__ __forceinline__ uint32_t smem_to_u32(const void* p) {
    uint32_t a;
    asm("{ .reg .u64 t; cvta.to.shared.u64 t, %1; cvt.u32.u64 %0, t; }" : "=r"(a) : "l"(p));
    return a;
}

#define CP16(dst, src) \
    asm volatile("cp.async.cg.shared.global [%0], [%1], 16;" :: "r"(dst), "l"(src))
#define CP_COMMIT() asm volatile("cp.async.commit_group;")
#define CP_WAIT0()  asm volatile("cp.async.wait_group 0;")
#define CP_WAIT1()  asm volatile("cp.async.wait_group 1;")

#define LDSM4(r, addr) \
    asm volatile("ldmatrix.sync.aligned.m8n8.x4.shared.b16 {%0,%1,%2,%3}, [%4];" \
        : "=r"((r)[0]), "=r"((r)[1]), "=r"((r)[2]), "=r"((r)[3]) : "r"(addr))

#define MMA16816(d, a, b) \
    asm volatile("mma.sync.aligned.m16n8k16.row.col.f32.bf16.bf16.f32 " \
        "{%0,%1,%2,%3}, {%4,%5,%6,%7}, {%8,%9}, {%0,%1,%2,%3};" \
        : "+f"((d)[0]), "+f"((d)[1]), "+f"((d)[2]), "+f"((d)[3]) \
        : "r"((a)[0]), "r"((a)[1]), "r"((a)[2]), "r"((a)[3]), \
          "r"((b)[0]), "r"((b)[1]))

// SMEM tile geometry: 128 rows x 32 bf16 (64B) + 16B pad => pitch 80B.
// Conflict-free for ldmatrix: 80*r mod 128 walks 8 distinct 16B slots.
#define TPITCH 80
#define TILE_B 10240            // 128 * 80
#define BUF_B  (4 * TILE_B)     // AH, AL, BH, BL = 40960
#define SMEM_TOTAL (2 * BUF_B)  // double-buffered = 81920

// ---------------------------------------------------------------------------
// Generic NT pair-GEMM on mma.sync bf16 (3-term hi/lo, fp32 accum):
//   C[m,n] = scale * sum_k A[m,k]*B[n,k]  (+ bias[n])
// mode 0: causal logits (skip nBase>mBase tiles, K=kFixed)
// mode 1: ctx (K = mBase+128 causal truncation)
// mode 2: plain (K = kFixed)
// outPair 0: fp32 C.  outPair 1: bf16 hi/lo (Ch, Cl).
// ---------------------------------------------------------------------------
__device__ __forceinline__ void stage_tile32(uint32_t sdst, const __nv_bfloat16* src,
                                             int ld, int tid) {
    #pragma unroll
    for (int it = 0; it < 2; it++) {
        int i = tid + it * 256;
        int row = i >> 2, seg = i & 3;
        CP16(sdst + row * TPITCH + seg * 16, src + (size_t)row * ld + seg * 8);
    }
}

__global__ __launch_bounds__(256, 2) void gemm_nt_mma(
    const __nv_bfloat16* __restrict__ Ah, const __nv_bfloat16* __restrict__ Al,
    const __nv_bfloat16* __restrict__ Bh, const __nv_bfloat16* __restrict__ Bl,
    float* __restrict__ C, __nv_bfloat16* __restrict__ Ch, __nv_bfloat16* __restrict__ Cl,
    const float* __restrict__ bias,
    int lda, int ldb, int ldc,
    size_t aBatch, size_t bBatch, size_t cBatch,
    int kFixed, int mode, int outPair, float scale)
{
    const int mBase = blockIdx.y * 128;
    const int nBase = blockIdx.x * 128;
    if (mode == 0 && nBase > mBase) return;        // fully masked logits tile
    const int b = blockIdx.z;
    const int kLen = (mode == 1) ? (mBase + 128) : kFixed;
    const int nChunks = kLen >> 5;

    const __nv_bfloat16* pAh = Ah + (size_t)b * aBatch + (size_t)mBase * lda;
    const __nv_bfloat16* pAl = Al + (size_t)b * aBatch + (size_t)mBase * lda;
    const __nv_bfloat16* pBh = Bh + (size_t)b * bBatch + (size_t)nBase * ldb;
    const __nv_bfloat16* pBl = Bl + (size_t)b * bBatch + (size_t)nBase * ldb;

    extern __shared__ char smem[];
    const uint32_t sb = smem_to_u32(smem);
    const int tid = threadIdx.x;
    const int lane = tid & 31, wid = tid >> 5;
    const int warp_m = (wid >> 2) * 64;            // 2 warps along M
    const int warp_n = (wid & 3) * 32;             // 4 warps along N

    const uint32_t aRowOff =
        (uint32_t)(warp_m + (lane & 15)) * TPITCH + (lane >> 4) * 16;
    const uint32_t bRowOff =
        (uint32_t)(warp_n + (lane & 7) + ((lane >> 4) & 1) * 8) * TPITCH
        + ((lane >> 3) & 1) * 16;

    float acc[4][4][4];
    #pragma unroll
    for (int i = 0; i < 4; i++)
        #pragma unroll
        for (int j = 0; j < 4; j++)
            #pragma unroll
            for (int t = 0; t < 4; t++) acc[i][j][t] = 0.f;

    // prefetch chunk 0 into buffer 0
    {
        stage_tile32(sb,              pAh, lda, tid);
        stage_tile32(sb + TILE_B,     pAl, lda, tid);
        stage_tile32(sb + 2 * TILE_B, pBh, ldb, tid);
        stage_tile32(sb + 3 * TILE_B, pBl, ldb, tid);
        CP_COMMIT();
    }

    for (int c = 0; c < nChunks; c++) {
        if (c + 1 < nChunks) {
            uint32_t s1 = sb + ((c + 1) & 1) * BUF_B;
            const int co = (c + 1) * 32;
            stage_tile32(s1,              pAh + co, lda, tid);
            stage_tile32(s1 + TILE_B,     pAl + co, lda, tid);
            stage_tile32(s1 + 2 * TILE_B, pBh + co, ldb, tid);
            stage_tile32(s1 + 3 * TILE_B, pBl + co, ldb, tid);
            CP_COMMIT();
            CP_WAIT1();
        } else {
            CP_WAIT0();
        }
        __syncthreads();

        const uint32_t s0 = sb + (c & 1) * BUF_B;
        #pragma unroll
        for (int kk = 0; kk < 2; kk++) {
            uint32_t arh[4][4], arl[4][4];
            const uint32_t kko = kk * 32;
            #pragma unroll
            for (int mi = 0; mi < 4; mi++) {
                LDSM4(arh[mi], s0 +          aRowOff + mi * (16 * TPITCH) + kko);
                LDSM4(arl[mi], s0 + TILE_B + aRowOff + mi * (16 * TPITCH) + kko);
            }
            #pragma unroll
            for (int g = 0; g < 2; g++) {
                uint32_t brh[4], brl[4];
                LDSM4(brh, s0 + 2 * TILE_B + bRowOff + g * (16 * TPITCH) + kko);
                LDSM4(brl, s0 + 3 * TILE_B + bRowOff + g * (16 * TPITCH) + kko);
                #pragma unroll
                for (int mi = 0; mi < 4; mi++)
                    #pragma unroll
                    for (int h = 0; h < 2; h++) {
                        const int nj = g * 2 + h;
                        MMA16816(acc[mi][nj], arh[mi], &brh[h * 2]);
                        MMA16816(acc[mi][nj], arh[mi], &brl[h * 2]);
                        MMA16816(acc[mi][nj], arl[mi], &brh[h * 2]);
                    }
            }
        }
        __syncthreads();
    }

    // Epilogue
    const int mrow = mBase + warp_m + (lane >> 2);
    const int ncol = nBase + warp_n + (lane & 3) * 2;
    float bv[4][2];
    #pragma unroll
    for (int nj = 0; nj < 4; nj++) {
        bv[nj][0] = bias ? bias[ncol + nj * 8]     : 0.f;
        bv[nj][1] = bias ? bias[ncol + nj * 8 + 1] : 0.f;
    }

    if (outPair == 0) {
        float* Cb = C + (size_t)b * cBatch;
        #pragma unroll
        for (int mi = 0; mi < 4; mi++)
            #pragma unroll
            for (int nj = 0; nj < 4; nj++) {
                const int m0 = mrow + mi * 16;
                const int n0 = ncol + nj * 8;
                float2 v0 = {acc[mi][nj][0] * scale + bv[nj][0],
                             acc[mi][nj][1] * scale + bv[nj][1]};
                float2 v1 = {acc[mi][nj][2] * scale + bv[nj][0],
                             acc[mi][nj][3] * scale + bv[nj][1]};
                *(float2*)&Cb[(size_t)m0 * ldc + n0] = v0;
                *(float2*)&Cb[(size_t)(m0 + 8) * ldc + n0] = v1;
            }
    } else {
        __nv_bfloat16* Chb = Ch + (size_t)b * cBatch;
        __nv_bfloat16* Clb = Cl + (size_t)b * cBatch;
        #pragma unroll
        for (int mi = 0; mi < 4; mi++)
            #pragma unroll
            for (int nj = 0; nj < 4; nj++) {
                const int m0 = mrow + mi * 16;
                const int n0 = ncol + nj * 8;
                #pragma unroll
                for (int half = 0; half < 2; half++) {
                    const int m = m0 + half * 8;
                    float x0 = acc[mi][nj][half * 2 + 0] * scale + bv[nj][0];
                    float x1 = acc[mi][nj][half * 2 + 1] * scale + bv[nj][1];
                    __nv_bfloat16 h0 = __float2bfloat16(x0);
                    __nv_bfloat16 h1 = __float2bfloat16(x1);
                    __nv_bfloat162 hh; hh.x = h0; hh.y = h1;
                    __nv_bfloat162 ll;
                    ll.x = __float2bfloat16(x0 - __bfloat162float(h0));
                    ll.y = __float2bfloat16(x1 - __bfloat162float(h1));
                    *(__nv_bfloat162*)&Chb[(size_t)m * ldc + n0] = hh;
                    *(__nv_bfloat162*)&Clb[(size_t)m * ldc + n0] = ll;
                }
            }
    }
}

// ---------------------------------------------------------------------------
// Fused fp32 -> bf16 hi/lo split for q, k, v in one launch
// ---------------------------------------------------------------------------
__global__ __launch_bounds__(256) void split3_kernel(
    const float* __restrict__ q, const float* __restrict__ k, const float* __restrict__ v,
    __nv_bfloat16* __restrict__ qh, __nv_bfloat16* __restrict__ ql,
    __nv_bfloat16* __restrict__ kh, __nv_bfloat16* __restrict__ kl,
    __nv_bfloat16* __restrict__ vh, __nv_bfloat16* __restrict__ vl, int n)
{
    for (int i = blockIdx.x * blockDim.x + threadIdx.x; i < n; i += gridDim.x * blockDim.x) {
        float a = q[i], b = k[i], c = v[i];
        __nv_bfloat16 ha = __float2bfloat16(a);
        __nv_bfloat16 hb = __float2bfloat16(b);
        __nv_bfloat16 hc = __float2bfloat16(c);
        qh[i] = ha; ql[i] = __float2bfloat16(a - __bfloat162float(ha));
        kh[i] = hb; kl[i] = __float2bfloat16(b - __bfloat162float(hb));
        vh[i] = hc; vl[i] = __float2bfloat16(c - __bfloat162float(hc));
    }
}

// ---------------------------------------------------------------------------
// All four W[k][n] -> Wt hi/lo [n][k] transpose-splits in one launch (z selects)
// ---------------------------------------------------------------------------
__global__ void wt4_kernel(
    const float* __restrict__ Wq, const float* __restrict__ Wk,
    const float* __restrict__ Wv, const float* __restrict__ Wo,
    __nv_bfloat16* __restrict__ qh, __nv_bfloat16* __restrict__ ql,
    __nv_bfloat16* __restrict__ kh, __nv_bfloat16* __restrict__ kl,
    __nv_bfloat16* __restrict__ vh, __nv_bfloat16* __restrict__ vl,
    __nv_bfloat16* __restrict__ oh, __nv_bfloat16* __restrict__ ol)
{
    const float* W;
    __nv_bfloat16 *th, *tl;
    switch (blockIdx.z) {
        case 0:  W = Wq; th = qh; tl = ql; break;
        case 1:  W = Wk; th = kh; tl = kl; break;
        case 2:  W = Wv; th = vh; tl = vl; break;
        default: W = Wo; th = oh; tl = ol; break;
    }
    __shared__ float t[32][33];
    const int k0 = blockIdx.x * 32, n0 = blockIdx.y * 32;
    #pragma unroll
    for (int i = 0; i < 32; i += 8)
        t[threadIdx.y + i][threadIdx.x] = W[(size_t)(k0 + threadIdx.y + i) * DD + n0 + threadIdx.x];
    __syncthreads();
    #pragma unroll
    for (int i = 0; i < 32; i += 8) {
        float x = t[threadIdx.x][threadIdx.y + i];
        __nv_bfloat16 hh = __float2bfloat16(x);
        size_t o = (size_t)(n0 + threadIdx.y + i) * DD + k0 + threadIdx.x;
        th[o] = hh;
        tl[o] = __float2bfloat16(x - __bfloat162float(hh));
    }
}

// ---------------------------------------------------------------------------
// Vp [b][s][d] -> Vp^T hi/lo [b][d][s]
// ---------------------------------------------------------------------------
__global__ __launch_bounds__(256) void transpose_split(
    const float* __restrict__ V, __nv_bfloat16* __restrict__ th,
    __nv_bfloat16* __restrict__ tl)
{
    __shared__ float t[32][33];
    const int b = blockIdx.z;
    const int s0 = blockIdx.x * 32, d0 = blockIdx.y * 32;
    const float* Vb = V + (size_t)b * SS * DD;
    #pragma unroll
    for (int i = 0; i < 32; i += 8)
        t[threadIdx.y + i][threadIdx.x] = Vb[(size_t)(s0 + threadIdx.y + i) * DD + d0 + threadIdx.x];
    __syncthreads();
    #pragma unroll
    for (int i = 0; i < 32; i += 8) {
        float x = t[threadIdx.x][threadIdx.y + i];
        __nv_bfloat16 hh = __float2bfloat16(x);
        size_t o = (size_t)b * DD * SS + (size_t)(d0 + threadIdx.y + i) * SS + s0 + threadIdx.x;
        th[o] = hh;
        tl[o] = __float2bfloat16(x - __bfloat162float(hh));
    }
}

// ---------------------------------------------------------------------------
// Row softmax in-place + emit attn hi/lo bf16 (only up to the diagonal tile
// boundary — ctx never reads beyond it). Zero-fills fp32 masked tail fully.
// ---------------------------------------------------------------------------
__global__ __launch_bounds__(256) void softmax_kernel(
    float* __restrict__ attn, __nv_bfloat16* __restrict__ ah,
    __nv_bfloat16* __restrict__ al)
{
    __shared__ float row[SS];
    __shared__ float red[256];
    const int gid = blockIdx.x;          // b*SS + q
    const int q = gid % SS;
    const size_t base = (size_t)gid * SS;
    float* r = attn + base;
    const int n = q + 1;
    const int kcap = ((q >> 7) + 1) << 7;   // ceil((q+1)/128)*128
    const int tid = threadIdx.x;

    float mx = -1e30f;
    for (int k = tid; k < n; k += 256) {
        float v = r[k];
        row[k] = v;
        mx = fmaxf(mx, v);
    }
    red[tid] = mx;
    __syncthreads();
    #pragma unroll
    for (int s = 128; s > 0; s >>= 1) {
        if (tid < s) red[tid] = fmaxf(red[tid], red[tid + s]);
        __syncthreads();
    }
    const float mxv = red[0];
    __syncthreads();

    float sum = 0.f;
    for (int k = tid; k < n; k += 256) {
        float e = expf(row[k] - mxv);
        row[k] = e;
        sum += e;
    }
    red[tid] = sum;
    __syncthreads();
    #pragma unroll
    for (int s = 128; s > 0; s >>= 1) {
        if (tid < s) red[tid] += red[tid + s];
        __syncthreads();
    }
    const float inv = 1.0f / red[0];

    for (int k = tid; k < n; k += 256) {
        float p = row[k] * inv;
        r[k] = p;
        __nv_bfloat16 h = __float2bfloat16(p);
        ah[base + k] = h;
        al[base + k] = __float2bfloat16(p - __bfloat162float(h));
    }
    const __nv_bfloat16 z = __float2bfloat16(0.0f);
    for (int k = n + tid; k < kcap; k += 256) {  // pairs: only to diagonal tile edge
        ah[base + k] = z;
        al[base + k] = z;
    }
    for (int k = n + tid; k < SS; k += 256) r[k] = 0.0f;  // fp32 output: full
}

// ---------------------------------------------------------------------------
extern "C" void kernel_launch(void* const* d_in, const int* in_sizes, int n_in,
                              void* d_out, int out_size)
{
    const float* q  = (const float*)d_in[0];
    const float* k  = (const float*)d_in[1];
    const float* v  = (const float*)d_in[2];
    // d_in[3] = mask (deterministic causal triu; handled analytically)
    const float* Wq = (const float*)d_in[4];
    const float* bq = (const float*)d_in[5];
    const float* Wk = (const float*)d_in[6];
    const float* bk = (const float*)d_in[7];
    const float* Wv = (const float*)d_in[8];
    const float* bv = (const float*)d_in[9];
    const float* Wo = (const float*)d_in[10];
    const float* bo = (const float*)d_in[11];

    float* z_out    = (float*)d_out;
    float* attn_out = z_out + (size_t)BB * SS * DD;

    __nv_bfloat16 *qh, *ql, *kh, *kl, *vh, *vl;
    __nv_bfloat16 *wqh, *wql, *wkh, *wkl, *wvh, *wvl, *woh, *wol;
    __nv_bfloat16 *qph, *qpl, *kph, *kpl, *vth, *vtl, *ah, *al, *cth, *ctl;
    float* vp;
    cudaGetSymbolAddress((void**)&qh, g_qh);   cudaGetSymbolAddress((void**)&ql, g_ql);
    cudaGetSymbolAddress((void**)&kh, g_kh);   cudaGetSymbolAddress((void**)&kl, g_kl);
    cudaGetSymbolAddress((void**)&vh, g_vh);   cudaGetSymbolAddress((void**)&vl, g_vl);
    cudaGetSymbolAddress((void**)&wqh, g_wqh); cudaGetSymbolAddress((void**)&wql, g_wql);
    cudaGetSymbolAddress((void**)&wkh, g_wkh); cudaGetSymbolAddress((void**)&wkl, g_wkl);
    cudaGetSymbolAddress((void**)&wvh, g_wvh); cudaGetSymbolAddress((void**)&wvl, g_wvl);
    cudaGetSymbolAddress((void**)&woh, g_woh); cudaGetSymbolAddress((void**)&wol, g_wol);
    cudaGetSymbolAddress((void**)&qph, g_qph); cudaGetSymbolAddress((void**)&qpl, g_qpl);
    cudaGetSymbolAddress((void**)&kph, g_kph); cudaGetSymbolAddress((void**)&kpl, g_kpl);
    cudaGetSymbolAddress((void**)&vth, g_vth); cudaGetSymbolAddress((void**)&vtl, g_vtl);
    cudaGetSymbolAddress((void**)&ah,  g_ah);  cudaGetSymbolAddress((void**)&al,  g_al);
    cudaGetSymbolAddress((void**)&cth, g_cth); cudaGetSymbolAddress((void**)&ctl, g_ctl);
    cudaGetSymbolAddress((void**)&vp,  g_vp);

    cudaFuncSetAttribute(gemm_nt_mma, cudaFuncAttributeMaxDynamicSharedMemorySize,
                         SMEM_TOTAL);

    dim3 blk(256);

    // (1) input splits, (2) weight transpose-splits
    split3_kernel<<<2048, blk>>>(q, k, v, qh, ql, kh, kl, vh, vl, MTOT * DD);
    wt4_kernel<<<dim3(8, 8, 4), dim3(32, 8)>>>(Wq, Wk, Wv, Wo,
        wqh, wql, wkh, wkl, wvh, wvl, woh, wol);

    // (3,4,5) projections
    dim3 gProj(DD / 128, MTOT / 128, 1);
    gemm_nt_mma<<<gProj, blk, SMEM_TOTAL>>>(
        qh, ql, wqh, wql, nullptr, qph, qpl, bq,
        DD, DD, DD, 0, 0, 0, DD, /*mode=*/2, /*outPair=*/1, 1.0f);
    gemm_nt_mma<<<gProj, blk, SMEM_TOTAL>>>(
        kh, kl, wkh, wkl, nullptr, kph, kpl, bk,
        DD, DD, DD, 0, 0, 0, DD, 2, 1, 1.0f);
    gemm_nt_mma<<<gProj, blk, SMEM_TOTAL>>>(
        vh, vl, wvh, wvl, vp, nullptr, nullptr, bv,
        DD, DD, DD, 0, 0, 0, DD, 2, 0, 1.0f);

    // (6) causal logits — profiled launch
    gemm_nt_mma<<<dim3(SS / 128, SS / 128, BB), blk, SMEM_TOTAL>>>(
        qph, qpl, kph, kpl, attn_out, nullptr, nullptr, nullptr,
        DD, DD, SS, (size_t)SS * DD, (size_t)SS * DD, (size_t)SS * SS,
        DD, /*mode=*/0, /*outPair=*/0, 0.0625f);

    // (7) Vp transpose + split
    transpose_split<<<dim3(SS / 32, DD / 32, BB), dim3(32, 8)>>>(vp, vth, vtl);

    // (8) softmax in-place + attn hi/lo pairs
    softmax_kernel<<<BB * SS, blk>>>(attn_out, ah, al);

    // (9) ctx = attn @ Vp (causal K truncation), bf16 pair output
    gemm_nt_mma<<<dim3(DD / 128, SS / 128, BB), blk, SMEM_TOTAL>>>(
        ah, al, vth, vtl, nullptr, cth, ctl, nullptr,
        SS, SS, DD, (size_t)SS * SS, (size_t)DD * SS, (size_t)SS * DD,
        0, /*mode=*/1, /*outPair=*/1, 1.0f);

    // (10) z = ctx @ Wo + bo
    gemm_nt_mma<<<gProj, blk, SMEM_TOTAL>>>(
        cth, ctl, woh, wol, z_out, nullptr, nullptr, bo,
        DD, DD, DD, 0, 0, 0, DD, 2, 0, 1.0f);
}

// round 7
// speedup vs baseline: 1.0411x; 1.0411x over previous
#include <cuda_runtime.h>
#include <cuda_bf16.h>
#include <math.h>
#include <stdint.h>

#define BB 4
#define SS 4096
#define DD 256
#define MTOT (BB*SS)

// ---------------------------------------------------------------------------
// Scratch (allocation-free rule: device globals)
// ---------------------------------------------------------------------------
__device__ __align__(16) __nv_bfloat16 g_qh[MTOT*DD],  g_ql[MTOT*DD];
__device__ __align__(16) __nv_bfloat16 g_kh[MTOT*DD],  g_kl[MTOT*DD];
__device__ __align__(16) __nv_bfloat16 g_vh[MTOT*DD],  g_vl[MTOT*DD];
__device__ __align__(16) __nv_bfloat16 g_wqh[DD*DD], g_wql[DD*DD];
__device__ __align__(16) __nv_bfloat16 g_wkh[DD*DD], g_wkl[DD*DD];
__device__ __align__(16) __nv_bfloat16 g_wvh[DD*DD], g_wvl[DD*DD];
__device__ __align__(16) __nv_bfloat16 g_woh[DD*DD], g_wol[DD*DD];
__device__ __align__(16) __nv_bfloat16 g_qph[MTOT*DD], g_qpl[MTOT*DD];
__device__ __align__(16) __nv_bfloat16 g_kph[MTOT*DD], g_kpl[MTOT*DD];
__device__ float g_vp[MTOT*DD];
__device__ __align__(16) __nv_bfloat16 g_vth[MTOT*DD], g_vtl[MTOT*DD];  // Vp^T [b][d][s]
__device__ __align__(16) __nv_bfloat16 g_ah[(size_t)BB*SS*SS], g_al[(size_t)BB*SS*SS];
__device__ __align__(16) __nv_bfloat16 g_cth[MTOT*DD], g_ctl[MTOT*DD];

// ---------------------------------------------------------------------------
// Portable-PTX helpers (compute_103-safe)
// ---------------------------------------------------------------------------
__device__ __forceinline__ uint32_t smem_to_u32(const void* p) {
    uint32_t a;
    asm("{ .reg .u64 t; cvta.to.shared.u64 t, %1; cvt.u32.u64 %0, t; }" : "=r"(a) : "l"(p));
    return a;
}

#define CP16(dst, src) \
    asm volatile("cp.async.cg.shared.global [%0], [%1], 16;" :: "r"(dst), "l"(src))
#define CP_COMMIT() asm volatile("cp.async.commit_group;")
#define CP_WAIT0()  asm volatile("cp.async.wait_group 0;")
#define CP_WAIT1()  asm volatile("cp.async.wait_group 1;")

#define LDSM4(r, addr) \
    asm volatile("ldmatrix.sync.aligned.m8n8.x4.shared.b16 {%0,%1,%2,%3}, [%4];" \
        : "=r"((r)[0]), "=r"((r)[1]), "=r"((r)[2]), "=r"((r)[3]) : "r"(addr))

#define MMA16816(d, a, b) \
    asm volatile("mma.sync.aligned.m16n8k16.row.col.f32.bf16.bf16.f32 " \
        "{%0,%1,%2,%3}, {%4,%5,%6,%7}, {%8,%9}, {%0,%1,%2,%3};" \
        : "+f"((d)[0]), "+f"((d)[1]), "+f"((d)[2]), "+f"((d)[3]) \
        : "r"((a)[0]), "r"((a)[1]), "r"((a)[2]), "r"((a)[3]), \
          "r"((b)[0]), "r"((b)[1]))

// SMEM tile geometry: 128 rows x 64 bf16, padded row stride 72 bf16 = 144 B.
// (Round-4 configuration: measured fastest — 1 CTA/SM, K-chunk 64.)
#define TPITCH 144
#define TILE_B 18432            // 128 * 144
#define BUF_B  (4 * TILE_B)     // AH, AL, BH, BL
#define SMEM_TOTAL (2 * BUF_B)  // double-buffered = 147456 B

// ---------------------------------------------------------------------------
// Generic NT pair-GEMM on mma.sync bf16 (3-term hi/lo, fp32 accum):
//   C[m,n] = scale * sum_k A[m,k]*B[n,k]  (+ bias[n])
// mode 0: causal logits (skip nBase>mBase tiles, K=kFixed)
// mode 1: ctx (K = mBase+128 causal truncation)
// mode 2: plain (K = kFixed)
// outPair 0: fp32 C.  outPair 1: bf16 hi/lo (Ch, Cl).
// ---------------------------------------------------------------------------
__device__ __forceinline__ void stage_tile(uint32_t sdst, const __nv_bfloat16* src,
                                           int ld, int tid) {
    #pragma unroll
    for (int it = 0; it < 4; it++) {
        int i = tid + it * 256;
        int row = i >> 3, seg = i & 7;
        CP16(sdst + row * TPITCH + seg * 16, src + (size_t)row * ld + seg * 8);
    }
}

__global__ __launch_bounds__(256) void gemm_nt_mma(
    const __nv_bfloat16* __restrict__ Ah, const __nv_bfloat16* __restrict__ Al,
    const __nv_bfloat16* __restrict__ Bh, const __nv_bfloat16* __restrict__ Bl,
    float* __restrict__ C, __nv_bfloat16* __restrict__ Ch, __nv_bfloat16* __restrict__ Cl,
    const float* __restrict__ bias,
    int lda, int ldb, int ldc,
    size_t aBatch, size_t bBatch, size_t cBatch,
    int kFixed, int mode, int outPair, float scale)
{
    const int mBase = blockIdx.y * 128;
    const int nBase = blockIdx.x * 128;
    if (mode == 0 && nBase > mBase) return;        // fully masked logits tile
    const int b = blockIdx.z;
    const int kLen = (mode == 1) ? (mBase + 128) : kFixed;
    const int nChunks = kLen >> 6;

    const __nv_bfloat16* pAh = Ah + (size_t)b * aBatch + (size_t)mBase * lda;
    const __nv_bfloat16* pAl = Al + (size_t)b * aBatch + (size_t)mBase * lda;
    const __nv_bfloat16* pBh = Bh + (size_t)b * bBatch + (size_t)nBase * ldb;
    const __nv_bfloat16* pBl = Bl + (size_t)b * bBatch + (size_t)nBase * ldb;

    extern __shared__ char smem[];
    const uint32_t sb = smem_to_u32(smem);
    const int tid = threadIdx.x;
    const int lane = tid & 31, wid = tid >> 5;
    const int warp_m = (wid >> 2) * 64;            // 2 warps along M
    const int warp_n = (wid & 3) * 32;             // 4 warps along N

    const uint32_t aRowOff =
        (uint32_t)(warp_m + (lane & 15)) * TPITCH + (lane >> 4) * 16;
    const uint32_t bRowOff =
        (uint32_t)(warp_n + (lane & 7) + ((lane >> 4) & 1) * 8) * TPITCH
        + ((lane >> 3) & 1) * 16;

    float acc[4][4][4];
    #pragma unroll
    for (int i = 0; i < 4; i++)
        #pragma unroll
        for (int j = 0; j < 4; j++)
            #pragma unroll
            for (int t = 0; t < 4; t++) acc[i][j][t] = 0.f;

    // prefetch chunk 0 into buffer 0
    {
        stage_tile(sb,              pAh, lda, tid);
        stage_tile(sb + TILE_B,     pAl, lda, tid);
        stage_tile(sb + 2 * TILE_B, pBh, ldb, tid);
        stage_tile(sb + 3 * TILE_B, pBl, ldb, tid);
        CP_COMMIT();
    }

    for (int c = 0; c < nChunks; c++) {
        if (c + 1 < nChunks) {
            uint32_t s1 = sb + ((c + 1) & 1) * BUF_B;
            const int co = (c + 1) * 64;
            stage_tile(s1,              pAh + co, lda, tid);
            stage_tile(s1 + TILE_B,     pAl + co, lda, tid);
            stage_tile(s1 + 2 * TILE_B, pBh + co, ldb, tid);
            stage_tile(s1 + 3 * TILE_B, pBl + co, ldb, tid);
            CP_COMMIT();
            CP_WAIT1();
        } else {
            CP_WAIT0();
        }
        __syncthreads();

        const uint32_t s0 = sb + (c & 1) * BUF_B;
        #pragma unroll
        for (int kk = 0; kk < 4; kk++) {
            uint32_t arh[4][4], arl[4][4];
            const uint32_t kko = kk * 32;
            #pragma unroll
            for (int mi = 0; mi < 4; mi++) {
                LDSM4(arh[mi], s0 +          aRowOff + mi * (16 * TPITCH) + kko);
                LDSM4(arl[mi], s0 + TILE_B + aRowOff + mi * (16 * TPITCH) + kko);
            }
            #pragma unroll
            for (int g = 0; g < 2; g++) {
                uint32_t brh[4], brl[4];
                LDSM4(brh, s0 + 2 * TILE_B + bRowOff + g * (16 * TPITCH) + kko);
                LDSM4(brl, s0 + 3 * TILE_B + bRowOff + g * (16 * TPITCH) + kko);
                #pragma unroll
                for (int mi = 0; mi < 4; mi++)
                    #pragma unroll
                    for (int h = 0; h < 2; h++) {
                        const int nj = g * 2 + h;
                        MMA16816(acc[mi][nj], arh[mi], &brh[h * 2]);
                        MMA16816(acc[mi][nj], arh[mi], &brl[h * 2]);
                        MMA16816(acc[mi][nj], arl[mi], &brh[h * 2]);
                    }
            }
        }
        __syncthreads();
    }

    // Epilogue
    const int mrow = mBase + warp_m + (lane >> 2);
    const int ncol = nBase + warp_n + (lane & 3) * 2;
    float bv[4][2];
    #pragma unroll
    for (int nj = 0; nj < 4; nj++) {
        bv[nj][0] = bias ? bias[ncol + nj * 8]     : 0.f;
        bv[nj][1] = bias ? bias[ncol + nj * 8 + 1] : 0.f;
    }

    if (outPair == 0) {
        float* Cb = C + (size_t)b * cBatch;
        #pragma unroll
        for (int mi = 0; mi < 4; mi++)
            #pragma unroll
            for (int nj = 0; nj < 4; nj++) {
                const int m0 = mrow + mi * 16;
                const int n0 = ncol + nj * 8;
                float2 v0 = {acc[mi][nj][0] * scale + bv[nj][0],
                             acc[mi][nj][1] * scale + bv[nj][1]};
                float2 v1 = {acc[mi][nj][2] * scale + bv[nj][0],
                             acc[mi][nj][3] * scale + bv[nj][1]};
                *(float2*)&Cb[(size_t)m0 * ldc + n0] = v0;
                *(float2*)&Cb[(size_t)(m0 + 8) * ldc + n0] = v1;
            }
    } else {
        __nv_bfloat16* Chb = Ch + (size_t)b * cBatch;
        __nv_bfloat16* Clb = Cl + (size_t)b * cBatch;
        #pragma unroll
        for (int mi = 0; mi < 4; mi++)
            #pragma unroll
            for (int nj = 0; nj < 4; nj++) {
                const int m0 = mrow + mi * 16;
                const int n0 = ncol + nj * 8;
                #pragma unroll
                for (int half = 0; half < 2; half++) {
                    const int m = m0 + half * 8;
                    float x0 = acc[mi][nj][half * 2 + 0] * scale + bv[nj][0];
                    float x1 = acc[mi][nj][half * 2 + 1] * scale + bv[nj][1];
                    __nv_bfloat16 h0 = __float2bfloat16(x0);
                    __nv_bfloat16 h1 = __float2bfloat16(x1);
                    __nv_bfloat162 hh; hh.x = h0; hh.y = h1;
                    __nv_bfloat162 ll;
                    ll.x = __float2bfloat16(x0 - __bfloat162float(h0));
                    ll.y = __float2bfloat16(x1 - __bfloat162float(h1));
                    *(__nv_bfloat162*)&Chb[(size_t)m * ldc + n0] = hh;
                    *(__nv_bfloat162*)&Clb[(size_t)m * ldc + n0] = ll;
                }
            }
    }
}

// ---------------------------------------------------------------------------
// Fused fp32 -> bf16 hi/lo split for q, k, v in one launch
// ---------------------------------------------------------------------------
__global__ __launch_bounds__(256) void split3_kernel(
    const float* __restrict__ q, const float* __restrict__ k, const float* __restrict__ v,
    __nv_bfloat16* __restrict__ qh, __nv_bfloat16* __restrict__ ql,
    __nv_bfloat16* __restrict__ kh, __nv_bfloat16* __restrict__ kl,
    __nv_bfloat16* __restrict__ vh, __nv_bfloat16* __restrict__ vl, int n)
{
    for (int i = blockIdx.x * blockDim.x + threadIdx.x; i < n; i += gridDim.x * blockDim.x) {
        float a = q[i], b = k[i], c = v[i];
        __nv_bfloat16 ha = __float2bfloat16(a);
        __nv_bfloat16 hb = __float2bfloat16(b);
        __nv_bfloat16 hc = __float2bfloat16(c);
        qh[i] = ha; ql[i] = __float2bfloat16(a - __bfloat162float(ha));
        kh[i] = hb; kl[i] = __float2bfloat16(b - __bfloat162float(hb));
        vh[i] = hc; vl[i] = __float2bfloat16(c - __bfloat162float(hc));
    }
}

// ---------------------------------------------------------------------------
// All four W[k][n] -> Wt hi/lo [n][k] transpose-splits in one launch (z selects)
// ---------------------------------------------------------------------------
__global__ void wt4_kernel(
    const float* __restrict__ Wq, const float* __restrict__ Wk,
    const float* __restrict__ Wv, const float* __restrict__ Wo,
    __nv_bfloat16* __restrict__ qh, __nv_bfloat16* __restrict__ ql,
    __nv_bfloat16* __restrict__ kh, __nv_bfloat16* __restrict__ kl,
    __nv_bfloat16* __restrict__ vh, __nv_bfloat16* __restrict__ vl,
    __nv_bfloat16* __restrict__ oh, __nv_bfloat16* __restrict__ ol)
{
    const float* W;
    __nv_bfloat16 *th, *tl;
    switch (blockIdx.z) {
        case 0:  W = Wq; th = qh; tl = ql; break;
        case 1:  W = Wk; th = kh; tl = kl; break;
        case 2:  W = Wv; th = vh; tl = vl; break;
        default: W = Wo; th = oh; tl = ol; break;
    }
    __shared__ float t[32][33];
    const int k0 = blockIdx.x * 32, n0 = blockIdx.y * 32;
    #pragma unroll
    for (int i = 0; i < 32; i += 8)
        t[threadIdx.y + i][threadIdx.x] = W[(size_t)(k0 + threadIdx.y + i) * DD + n0 + threadIdx.x];
    __syncthreads();
    #pragma unroll
    for (int i = 0; i < 32; i += 8) {
        float x = t[threadIdx.x][threadIdx.y + i];
        __nv_bfloat16 hh = __float2bfloat16(x);
        size_t o = (size_t)(n0 + threadIdx.y + i) * DD + k0 + threadIdx.x;
        th[o] = hh;
        tl[o] = __float2bfloat16(x - __bfloat162float(hh));
    }
}

// ---------------------------------------------------------------------------
// Vp [b][s][d] -> Vp^T hi/lo [b][d][s]
// ---------------------------------------------------------------------------
__global__ __launch_bounds__(256) void transpose_split(
    const float* __restrict__ V, __nv_bfloat16* __restrict__ th,
    __nv_bfloat16* __restrict__ tl)
{
    __shared__ float t[32][33];
    const int b = blockIdx.z;
    const int s0 = blockIdx.x * 32, d0 = blockIdx.y * 32;
    const float* Vb = V + (size_t)b * SS * DD;
    #pragma unroll
    for (int i = 0; i < 32; i += 8)
        t[threadIdx.y + i][threadIdx.x] = Vb[(size_t)(s0 + threadIdx.y + i) * DD + d0 + threadIdx.x];
    __syncthreads();
    #pragma unroll
    for (int i = 0; i < 32; i += 8) {
        float x = t[threadIdx.x][threadIdx.y + i];
        __nv_bfloat16 hh = __float2bfloat16(x);
        size_t o = (size_t)b * DD * SS + (size_t)(d0 + threadIdx.y + i) * SS + s0 + threadIdx.x;
        th[o] = hh;
        tl[o] = __float2bfloat16(x - __bfloat162float(hh));
    }
}

// ---------------------------------------------------------------------------
// Row softmax in-place + emit attn hi/lo bf16 (only up to the diagonal tile
// boundary — ctx never reads beyond it). Zero-fills fp32 masked tail fully.
// ---------------------------------------------------------------------------
__global__ __launch_bounds__(256) void softmax_kernel(
    float* __restrict__ attn, __nv_bfloat16* __restrict__ ah,
    __nv_bfloat16* __restrict__ al)
{
    __shared__ float row[SS];
    __shared__ float red[256];
    const int gid = blockIdx.x;          // b*SS + q
    const int q = gid % SS;
    const size_t base = (size_t)gid * SS;
    float* r = attn + base;
    const int n = q + 1;
    const int kcap = ((q >> 7) + 1) << 7;   // ceil((q+1)/128)*128
    const int tid = threadIdx.x;

    float mx = -1e30f;
    for (int k = tid; k < n; k += 256) {
        float v = r[k];
        row[k] = v;
        mx = fmaxf(mx, v);
    }
    red[tid] = mx;
    __syncthreads();
    #pragma unroll
    for (int s = 128; s > 0; s >>= 1) {
        if (tid < s) red[tid] = fmaxf(red[tid], red[tid + s]);
        __syncthreads();
    }
    const float mxv = red[0];
    __syncthreads();

    float sum = 0.f;
    for (int k = tid; k < n; k += 256) {
        float e = expf(row[k] - mxv);
        row[k] = e;
        sum += e;
    }
    red[tid] = sum;
    __syncthreads();
    #pragma unroll
    for (int s = 128; s > 0; s >>= 1) {
        if (tid < s) red[tid] += red[tid + s];
        __syncthreads();
    }
    const float inv = 1.0f / red[0];

    for (int k = tid; k < n; k += 256) {
        float p = row[k] * inv;
        r[k] = p;
        __nv_bfloat16 h = __float2bfloat16(p);
        ah[base + k] = h;
        al[base + k] = __float2bfloat16(p - __bfloat162float(h));
    }
    const __nv_bfloat16 z = __float2bfloat16(0.0f);
    for (int k = n + tid; k < kcap; k += 256) {  // pairs: only to diagonal tile edge
        ah[base + k] = z;
        al[base + k] = z;
    }
    for (int k = n + tid; k < SS; k += 256) r[k] = 0.0f;  // fp32 output: full
}

// ---------------------------------------------------------------------------
extern "C" void kernel_launch(void* const* d_in, const int* in_sizes, int n_in,
                              void* d_out, int out_size)
{
    const float* q  = (const float*)d_in[0];
    const float* k  = (const float*)d_in[1];
    const float* v  = (const float*)d_in[2];
    // d_in[3] = mask (deterministic causal triu; handled analytically)
    const float* Wq = (const float*)d_in[4];
    const float* bq = (const float*)d_in[5];
    const float* Wk = (const float*)d_in[6];
    const float* bk = (const float*)d_in[7];
    const float* Wv = (const float*)d_in[8];
    const float* bv = (const float*)d_in[9];
    const float* Wo = (const float*)d_in[10];
    const float* bo = (const float*)d_in[11];

    float* z_out    = (float*)d_out;
    float* attn_out = z_out + (size_t)BB * SS * DD;

    __nv_bfloat16 *qh, *ql, *kh, *kl, *vh, *vl;
    __nv_bfloat16 *wqh, *wql, *wkh, *wkl, *wvh, *wvl, *woh, *wol;
    __nv_bfloat16 *qph, *qpl, *kph, *kpl, *vth, *vtl, *ah, *al, *cth, *ctl;
    float* vp;
    cudaGetSymbolAddress((void**)&qh, g_qh);   cudaGetSymbolAddress((void**)&ql, g_ql);
    cudaGetSymbolAddress((void**)&kh, g_kh);   cudaGetSymbolAddress((void**)&kl, g_kl);
    cudaGetSymbolAddress((void**)&vh, g_vh);   cudaGetSymbolAddress((void**)&vl, g_vl);
    cudaGetSymbolAddress((void**)&wqh, g_wqh); cudaGetSymbolAddress((void**)&wql, g_wql);
    cudaGetSymbolAddress((void**)&wkh, g_wkh); cudaGetSymbolAddress((void**)&wkl, g_wkl);
    cudaGetSymbolAddress((void**)&wvh, g_wvh); cudaGetSymbolAddress((void**)&wvl, g_wvl);
    cudaGetSymbolAddress((void**)&woh, g_woh); cudaGetSymbolAddress((void**)&wol, g_wol);
    cudaGetSymbolAddress((void**)&qph, g_qph); cudaGetSymbolAddress((void**)&qpl, g_qpl);
    cudaGetSymbolAddress((void**)&kph, g_kph); cudaGetSymbolAddress((void**)&kpl, g_kpl);
    cudaGetSymbolAddress((void**)&vth, g_vth); cudaGetSymbolAddress((void**)&vtl, g_vtl);
    cudaGetSymbolAddress((void**)&ah,  g_ah);  cudaGetSymbolAddress((void**)&al,  g_al);
    cudaGetSymbolAddress((void**)&cth, g_cth); cudaGetSymbolAddress((void**)&ctl, g_ctl);
    cudaGetSymbolAddress((void**)&vp,  g_vp);

    cudaFuncSetAttribute(gemm_nt_mma, cudaFuncAttributeMaxDynamicSharedMemorySize,
                         SMEM_TOTAL);

    dim3 blk(256);

    // (1) input splits, (2) weight transpose-splits
    split3_kernel<<<2048, blk>>>(q, k, v, qh, ql, kh, kl, vh, vl, MTOT * DD);
    wt4_kernel<<<dim3(8, 8, 4), dim3(32, 8)>>>(Wq, Wk, Wv, Wo,
        wqh, wql, wkh, wkl, wvh, wvl, woh, wol);

    // (3,4,5) projections
    dim3 gProj(DD / 128, MTOT / 128, 1);
    gemm_nt_mma<<<gProj, blk, SMEM_TOTAL>>>(
        qh, ql, wqh, wql, nullptr, qph, qpl, bq,
        DD, DD, DD, 0, 0, 0, DD, /*mode=*/2, /*outPair=*/1, 1.0f);
    gemm_nt_mma<<<gProj, blk, SMEM_TOTAL>>>(
        kh, kl, wkh, wkl, nullptr, kph, kpl, bk,
        DD, DD, DD, 0, 0, 0, DD, 2, 1, 1.0f);
    gemm_nt_mma<<<gProj, blk, SMEM_TOTAL>>>(
        vh, vl, wvh, wvl, vp, nullptr, nullptr, bv,
        DD, DD, DD, 0, 0, 0, DD, 2, 0, 1.0f);

    // (6) causal logits
    gemm_nt_mma<<<dim3(SS / 128, SS / 128, BB), blk, SMEM_TOTAL>>>(
        qph, qpl, kph, kpl, attn_out, nullptr, nullptr, nullptr,
        DD, DD, SS, (size_t)SS * DD, (size_t)SS * DD, (size_t)SS * SS,
        DD, /*mode=*/0, /*outPair=*/0, 0.0625f);

    // (7) Vp transpose + split
    transpose_split<<<dim3(SS / 32, DD / 32, BB), dim3(32, 8)>>>(vp, vth, vtl);

    // (8) softmax in-place + attn hi/lo pairs
    softmax_kernel<<<BB * SS, blk>>>(attn_out, ah, al);

    // (9) ctx = attn @ Vp (causal K truncation), bf16 pair output
    gemm_nt_mma<<<dim3(DD / 128, SS / 128, BB), blk, SMEM_TOTAL>>>(
        ah, al, vth, vtl, nullptr, cth, ctl, nullptr,
        SS, SS, DD, (size_t)SS * SS, (size_t)DD * SS, (size_t)SS * DD,
        0, /*mode=*/1, /*outPair=*/1, 1.0f);

    // (10) z = ctx @ Wo + bo
    gemm_nt_mma<<<gProj, blk, SMEM_TOTAL>>>(
        cth, ctl, woh, wol, z_out, nullptr, nullptr, bo,
        DD, DD, DD, 0, 0, 0, DD, 2, 0, 1.0f);
}

// round 10
// speedup vs baseline: 1.5683x; 1.5064x over previous
#include <cuda_runtime.h>
#include <cuda_bf16.h>
#include <math.h>
#include <stdint.h>

#define BB 4
#define SS 4096
#define DD 256
#define MTOT (BB*SS)

// ---------------------------------------------------------------------------
// Scratch (allocation-free rule: device globals)
// ---------------------------------------------------------------------------
__device__ __align__(16) __nv_bfloat16 g_qh[MTOT*DD],  g_ql[MTOT*DD];
__device__ __align__(16) __nv_bfloat16 g_kh[MTOT*DD],  g_kl[MTOT*DD];
__device__ __align__(16) __nv_bfloat16 g_vh[MTOT*DD],  g_vl[MTOT*DD];
__device__ __align__(16) __nv_bfloat16 g_wqh[DD*DD], g_wql[DD*DD];
__device__ __align__(16) __nv_bfloat16 g_wkh[DD*DD], g_wkl[DD*DD];
__device__ __align__(16) __nv_bfloat16 g_wvh[DD*DD], g_wvl[DD*DD];
__device__ __align__(16) __nv_bfloat16 g_woh[DD*DD], g_wol[DD*DD];
__device__ __align__(16) __nv_bfloat16 g_qph[MTOT*DD], g_qpl[MTOT*DD];
__device__ __align__(16) __nv_bfloat16 g_kph[MTOT*DD], g_kpl[MTOT*DD];
__device__ float g_vp[MTOT*DD];
__device__ __align__(16) __nv_bfloat16 g_vth[MTOT*DD], g_vtl[MTOT*DD];  // Vp^T [b][d][s]
__device__ __align__(16) __nv_bfloat16 g_ah[(size_t)BB*SS*SS], g_al[(size_t)BB*SS*SS];
__device__ __align__(16) __nv_bfloat16 g_cth[MTOT*DD], g_ctl[MTOT*DD];

// ---------------------------------------------------------------------------
// Portable-PTX helpers (compute_103-safe)
// ---------------------------------------------------------------------------
__device__ __forceinline__ uint32_t smem_to_u32(const void* p) {
    uint32_t a;
    asm("{ .reg .u64 t; cvta.to.shared.u64 t, %1; cvt.u32.u64 %0, t; }" : "=r"(a) : "l"(p));
    return a;
}

#define CP16(dst, src) \
    asm volatile("cp.async.cg.shared.global [%0], [%1], 16;" :: "r"(dst), "l"(src))
#define CP_COMMIT() asm volatile("cp.async.commit_group;")
#define CP_WAIT0()  asm volatile("cp.async.wait_group 0;")
#define CP_WAIT1()  asm volatile("cp.async.wait_group 1;")

#define LDSM4(r, addr) \
    asm volatile("ldmatrix.sync.aligned.m8n8.x4.shared.b16 {%0,%1,%2,%3}, [%4];" \
        : "=r"((r)[0]), "=r"((r)[1]), "=r"((r)[2]), "=r"((r)[3]) : "r"(addr))

#define MMA16816(d, a, b) \
    asm volatile("mma.sync.aligned.m16n8k16.row.col.f32.bf16.bf16.f32 " \
        "{%0,%1,%2,%3}, {%4,%5,%6,%7}, {%8,%9}, {%0,%1,%2,%3};" \
        : "+f"((d)[0]), "+f"((d)[1]), "+f"((d)[2]), "+f"((d)[3]) \
        : "r"((a)[0]), "r"((a)[1]), "r"((a)[2]), "r"((a)[3]), \
          "r"((b)[0]), "r"((b)[1]))

// SMEM tile geometry: 128 rows x 64 bf16, padded row stride 72 bf16 = 144 B.
#define TPITCH 144
#define TILE_B 18432            // 128 * 144
#define BUF_B  (4 * TILE_B)     // AH, AL, BH, BL
#define SMEM_TOTAL (2 * BUF_B)  // double-buffered = 147456 B

#define NTHR 512                // 16 warps: 4 (M) x 4 (N), 32x32 warp tiles

// ---------------------------------------------------------------------------
// Generic NT pair-GEMM on mma.sync bf16 (3-term hi/lo, fp32 accum):
//   C[m,n] = scale * sum_k A[m,k]*B[n,k]  (+ bias[n])
// mode 0: causal logits (skip nBase>mBase tiles, K=kFixed)
// mode 1: ctx (K = mBase+128 causal truncation)
// mode 2: plain (K = kFixed)
// outPair 0: fp32 C.  outPair 1: bf16 hi/lo (Ch, Cl).
// ---------------------------------------------------------------------------
__device__ __forceinline__ void stage_tile(uint32_t sdst, const __nv_bfloat16* src,
                                           int ld, int tid) {
    #pragma unroll
    for (int it = 0; it < 2; it++) {
        int i = tid + it * NTHR;
        int row = i >> 3, seg = i & 7;
        CP16(sdst + row * TPITCH + seg * 16, src + (size_t)row * ld + seg * 8);
    }
}

__global__ __launch_bounds__(NTHR) void gemm_nt_mma(
    const __nv_bfloat16* __restrict__ Ah, const __nv_bfloat16* __restrict__ Al,
    const __nv_bfloat16* __restrict__ Bh, const __nv_bfloat16* __restrict__ Bl,
    float* __restrict__ C, __nv_bfloat16* __restrict__ Ch, __nv_bfloat16* __restrict__ Cl,
    const float* __restrict__ bias,
    int lda, int ldb, int ldc,
    size_t aBatch, size_t bBatch, size_t cBatch,
    int kFixed, int mode, int outPair, float scale)
{
    const int mBase = blockIdx.y * 128;
    const int nBase = blockIdx.x * 128;
    if (mode == 0 && nBase > mBase) return;        // fully masked logits tile
    const int b = blockIdx.z;
    const int kLen = (mode == 1) ? (mBase + 128) : kFixed;
    const int nChunks = kLen >> 6;

    const __nv_bfloat16* pAh = Ah + (size_t)b * aBatch + (size_t)mBase * lda;
    const __nv_bfloat16* pAl = Al + (size_t)b * aBatch + (size_t)mBase * lda;
    const __nv_bfloat16* pBh = Bh + (size_t)b * bBatch + (size_t)nBase * ldb;
    const __nv_bfloat16* pBl = Bl + (size_t)b * bBatch + (size_t)nBase * ldb;

    extern __shared__ char smem[];
    const uint32_t sb = smem_to_u32(smem);
    const int tid = threadIdx.x;
    const int lane = tid & 31, wid = tid >> 5;
    const int warp_m = (wid & 3) * 32;             // 4 warps along M
    const int warp_n = (wid >> 2) * 32;            // 4 warps along N

    const uint32_t aRowOff =
        (uint32_t)(warp_m + (lane & 15)) * TPITCH + (lane >> 4) * 16;
    const uint32_t bRowOff =
        (uint32_t)(warp_n + (lane & 7) + ((lane >> 4) & 1) * 8) * TPITCH
        + ((lane >> 3) & 1) * 16;

    float acc[2][4][4];
    #pragma unroll
    for (int i = 0; i < 2; i++)
        #pragma unroll
        for (int j = 0; j < 4; j++)
            #pragma unroll
            for (int t = 0; t < 4; t++) acc[i][j][t] = 0.f;

    // prefetch chunk 0 into buffer 0
    {
        stage_tile(sb,              pAh, lda, tid);
        stage_tile(sb + TILE_B,     pAl, lda, tid);
        stage_tile(sb + 2 * TILE_B, pBh, ldb, tid);
        stage_tile(sb + 3 * TILE_B, pBl, ldb, tid);
        CP_COMMIT();
    }

    for (int c = 0; c < nChunks; c++) {
        if (c + 1 < nChunks) {
            uint32_t s1 = sb + ((c + 1) & 1) * BUF_B;
            const int co = (c + 1) * 64;
            stage_tile(s1,              pAh + co, lda, tid);
            stage_tile(s1 + TILE_B,     pAl + co, lda, tid);
            stage_tile(s1 + 2 * TILE_B, pBh + co, ldb, tid);
            stage_tile(s1 + 3 * TILE_B, pBl + co, ldb, tid);
            CP_COMMIT();
            CP_WAIT1();
        } else {
            CP_WAIT0();
        }
        __syncthreads();

        const uint32_t s0 = sb + (c & 1) * BUF_B;
        #pragma unroll
        for (int kk = 0; kk < 4; kk++) {
            uint32_t arh[2][4], arl[2][4], brh[2][4], brl[2][4];
            const uint32_t kko = kk * 32;
            #pragma unroll
            for (int mi = 0; mi < 2; mi++) {
                LDSM4(arh[mi], s0 +          aRowOff + mi * (16 * TPITCH) + kko);
                LDSM4(arl[mi], s0 + TILE_B + aRowOff + mi * (16 * TPITCH) + kko);
            }
            #pragma unroll
            for (int g = 0; g < 2; g++) {
                LDSM4(brh[g], s0 + 2 * TILE_B + bRowOff + g * (16 * TPITCH) + kko);
                LDSM4(brl[g], s0 + 3 * TILE_B + bRowOff + g * (16 * TPITCH) + kko);
            }
            #pragma unroll
            for (int mi = 0; mi < 2; mi++)
                #pragma unroll
                for (int g = 0; g < 2; g++)
                    #pragma unroll
                    for (int h = 0; h < 2; h++) {
                        const int nj = g * 2 + h;
                        MMA16816(acc[mi][nj], arh[mi], &brh[g][h * 2]);
                        MMA16816(acc[mi][nj], arh[mi], &brl[g][h * 2]);
                        MMA16816(acc[mi][nj], arl[mi], &brh[g][h * 2]);
                    }
        }
        __syncthreads();
    }

    // Epilogue: warp covers 32(M) x 32(N); rows mrow+{0,8,16,24}
    const int mrow = mBase + warp_m + (lane >> 2);
    const int ncol = nBase + warp_n + (lane & 3) * 2;
    float bv[4][2];
    #pragma unroll
    for (int nj = 0; nj < 4; nj++) {
        bv[nj][0] = bias ? bias[ncol + nj * 8]     : 0.f;
        bv[nj][1] = bias ? bias[ncol + nj * 8 + 1] : 0.f;
    }

    if (outPair == 0) {
        float* Cb = C + (size_t)b * cBatch;
        #pragma unroll
        for (int mi = 0; mi < 2; mi++)
            #pragma unroll
            for (int nj = 0; nj < 4; nj++) {
                const int m0 = mrow + mi * 16;
                const int n0 = ncol + nj * 8;
                float2 v0 = {acc[mi][nj][0] * scale + bv[nj][0],
                             acc[mi][nj][1] * scale + bv[nj][1]};
                float2 v1 = {acc[mi][nj][2] * scale + bv[nj][0],
                             acc[mi][nj][3] * scale + bv[nj][1]};
                *(float2*)&Cb[(size_t)m0 * ldc + n0] = v0;
                *(float2*)&Cb[(size_t)(m0 + 8) * ldc + n0] = v1;
            }
    } else {
        __nv_bfloat16* Chb = Ch + (size_t)b * cBatch;
        __nv_bfloat16* Clb = Cl + (size_t)b * cBatch;
        #pragma unroll
        for (int mi = 0; mi < 2; mi++)
            #pragma unroll
            for (int nj = 0; nj < 4; nj++) {
                const int m0 = mrow + mi * 16;
                const int n0 = ncol + nj * 8;
                #pragma unroll
                for (int half = 0; half < 2; half++) {
                    const int m = m0 + half * 8;
                    float x0 = acc[mi][nj][half * 2 + 0] * scale + bv[nj][0];
                    float x1 = acc[mi][nj][half * 2 + 1] * scale + bv[nj][1];
                    __nv_bfloat16 h0 = __float2bfloat16(x0);
                    __nv_bfloat16 h1 = __float2bfloat16(x1);
                    __nv_bfloat162 hh; hh.x = h0; hh.y = h1;
                    __nv_bfloat162 ll;
                    ll.x = __float2bfloat16(x0 - __bfloat162float(h0));
                    ll.y = __float2bfloat16(x1 - __bfloat162float(h1));
                    *(__nv_bfloat162*)&Chb[(size_t)m * ldc + n0] = hh;
                    *(__nv_bfloat162*)&Clb[(size_t)m * ldc + n0] = ll;
                }
            }
    }
}

// ---------------------------------------------------------------------------
// Fused fp32 -> bf16 hi/lo split for q, k, v in one launch
// ---------------------------------------------------------------------------
__global__ __launch_bounds__(256) void split3_kernel(
    const float* __restrict__ q, const float* __restrict__ k, const float* __restrict__ v,
    __nv_bfloat16* __restrict__ qh, __nv_bfloat16* __restrict__ ql,
    __nv_bfloat16* __restrict__ kh, __nv_bfloat16* __restrict__ kl,
    __nv_bfloat16* __restrict__ vh, __nv_bfloat16* __restrict__ vl, int n)
{
    for (int i = blockIdx.x * blockDim.x + threadIdx.x; i < n; i += gridDim.x * blockDim.x) {
        float a = q[i], b = k[i], c = v[i];
        __nv_bfloat16 ha = __float2bfloat16(a);
        __nv_bfloat16 hb = __float2bfloat16(b);
        __nv_bfloat16 hc = __float2bfloat16(c);
        qh[i] = ha; ql[i] = __float2bfloat16(a - __bfloat162float(ha));
        kh[i] = hb; kl[i] = __float2bfloat16(b - __bfloat162float(hb));
        vh[i] = hc; vl[i] = __float2bfloat16(c - __bfloat162float(hc));
    }
}

// ---------------------------------------------------------------------------
// All four W[k][n] -> Wt hi/lo [n][k] transpose-splits in one launch (z selects)
// ---------------------------------------------------------------------------
__global__ void wt4_kernel(
    const float* __restrict__ Wq, const float* __restrict__ Wk,
    const float* __restrict__ Wv, const float* __restrict__ Wo,
    __nv_bfloat16* __restrict__ qh, __nv_bfloat16* __restrict__ ql,
    __nv_bfloat16* __restrict__ kh, __nv_bfloat16* __restrict__ kl,
    __nv_bfloat16* __restrict__ vh, __nv_bfloat16* __restrict__ vl,
    __nv_bfloat16* __restrict__ oh, __nv_bfloat16* __restrict__ ol)
{
    const float* W;
    __nv_bfloat16 *th, *tl;
    switch (blockIdx.z) {
        case 0:  W = Wq; th = qh; tl = ql; break;
        case 1:  W = Wk; th = kh; tl = kl; break;
        case 2:  W = Wv; th = vh; tl = vl; break;
        default: W = Wo; th = oh; tl = ol; break;
    }
    __shared__ float t[32][33];
    const int k0 = blockIdx.x * 32, n0 = blockIdx.y * 32;
    #pragma unroll
    for (int i = 0; i < 32; i += 8)
        t[threadIdx.y + i][threadIdx.x] = W[(size_t)(k0 + threadIdx.y + i) * DD + n0 + threadIdx.x];
    __syncthreads();
    #pragma unroll
    for (int i = 0; i < 32; i += 8) {
        float x = t[threadIdx.x][threadIdx.y + i];
        __nv_bfloat16 hh = __float2bfloat16(x);
        size_t o = (size_t)(n0 + threadIdx.y + i) * DD + k0 + threadIdx.x;
        th[o] = hh;
        tl[o] = __float2bfloat16(x - __bfloat162float(hh));
    }
}

// ---------------------------------------------------------------------------
// Vp [b][s][d] -> Vp^T hi/lo [b][d][s]
// ---------------------------------------------------------------------------
__global__ __launch_bounds__(256) void transpose_split(
    const float* __restrict__ V, __nv_bfloat16* __restrict__ th,
    __nv_bfloat16* __restrict__ tl)
{
    __shared__ float t[32][33];
    const int b = blockIdx.z;
    const int s0 = blockIdx.x * 32, d0 = blockIdx.y * 32;
    const float* Vb = V + (size_t)b * SS * DD;
    #pragma unroll
    for (int i = 0; i < 32; i += 8)
        t[threadIdx.y + i][threadIdx.x] = Vb[(size_t)(s0 + threadIdx.y + i) * DD + d0 + threadIdx.x];
    __syncthreads();
    #pragma unroll
    for (int i = 0; i < 32; i += 8) {
        float x = t[threadIdx.x][threadIdx.y + i];
        __nv_bfloat16 hh = __float2bfloat16(x);
        size_t o = (size_t)b * DD * SS + (size_t)(d0 + threadIdx.y + i) * SS + s0 + threadIdx.x;
        th[o] = hh;
        tl[o] = __float2bfloat16(x - __bfloat162float(hh));
    }
}

// ---------------------------------------------------------------------------
// Row softmax in-place + emit attn hi/lo bf16 (only up to the diagonal tile
// boundary — ctx never reads beyond it). Zero-fills fp32 masked tail fully.
// ---------------------------------------------------------------------------
__global__ __launch_bounds__(256) void softmax_kernel(
    float* __restrict__ attn, __nv_bfloat16* __restrict__ ah,
    __nv_bfloat16* __restrict__ al)
{
    __shared__ float row[SS];
    __shared__ float red[256];
    const int gid = blockIdx.x;          // b*SS + q
    const int q = gid % SS;
    const size_t base = (size_t)gid * SS;
    float* r = attn + base;
    const int n = q + 1;
    const int kcap = ((q >> 7) + 1) << 7;   // ceil((q+1)/128)*128
    const int tid = threadIdx.x;

    float mx = -1e30f;
    for (int k = tid; k < n; k += 256) {
        float v = r[k];
        row[k] = v;
        mx = fmaxf(mx, v);
    }
    red[tid] = mx;
    __syncthreads();
    #pragma unroll
    for (int s = 128; s > 0; s >>= 1) {
        if (tid < s) red[tid] = fmaxf(red[tid], red[tid + s]);
        __syncthreads();
    }
    const float mxv = red[0];
    __syncthreads();

    float sum = 0.f;
    for (int k = tid; k < n; k += 256) {
        float e = expf(row[k] - mxv);
        row[k] = e;
        sum += e;
    }
    red[tid] = sum;
    __syncthreads();
    #pragma unroll
    for (int s = 128; s > 0; s >>= 1) {
        if (tid < s) red[tid] += red[tid + s];
        __syncthreads();
    }
    const float inv = 1.0f / red[0];

    for (int k = tid; k < n; k += 256) {
        float p = row[k] * inv;
        r[k] = p;
        __nv_bfloat16 h = __float2bfloat16(p);
        ah[base + k] = h;
        al[base + k] = __float2bfloat16(p - __bfloat162float(h));
    }
    const __nv_bfloat16 z = __float2bfloat16(0.0f);
    for (int k = n + tid; k < kcap; k += 256) {  // pairs: only to diagonal tile edge
        ah[base + k] = z;
        al[base + k] = z;
    }
    for (int k = n + tid; k < SS; k += 256) r[k] = 0.0f;  // fp32 output: full
}

// ---------------------------------------------------------------------------
extern "C" void kernel_launch(void* const* d_in, const int* in_sizes, int n_in,
                              void* d_out, int out_size)
{
    const float* q  = (const float*)d_in[0];
    const float* k  = (const float*)d_in[1];
    const float* v  = (const float*)d_in[2];
    // d_in[3] = mask (deterministic causal triu; handled analytically)
    const float* Wq = (const float*)d_in[4];
    const float* bq = (const float*)d_in[5];
    const float* Wk = (const float*)d_in[6];
    const float* bk = (const float*)d_in[7];
    const float* Wv = (const float*)d_in[8];
    const float* bv = (const float*)d_in[9];
    const float* Wo = (const float*)d_in[10];
    const float* bo = (const float*)d_in[11];

    float* z_out    = (float*)d_out;
    float* attn_out = z_out + (size_t)BB * SS * DD;

    __nv_bfloat16 *qh, *ql, *kh, *kl, *vh, *vl;
    __nv_bfloat16 *wqh, *wql, *wkh, *wkl, *wvh, *wvl, *woh, *wol;
    __nv_bfloat16 *qph, *qpl, *kph, *kpl, *vth, *vtl, *ah, *al, *cth, *ctl;
    float* vp;
    cudaGetSymbolAddress((void**)&qh, g_qh);   cudaGetSymbolAddress((void**)&ql, g_ql);
    cudaGetSymbolAddress((void**)&kh, g_kh);   cudaGetSymbolAddress((void**)&kl, g_kl);
    cudaGetSymbolAddress((void**)&vh, g_vh);   cudaGetSymbolAddress((void**)&vl, g_vl);
    cudaGetSymbolAddress((void**)&wqh, g_wqh); cudaGetSymbolAddress((void**)&wql, g_wql);
    cudaGetSymbolAddress((void**)&wkh, g_wkh); cudaGetSymbolAddress((void**)&wkl, g_wkl);
    cudaGetSymbolAddress((void**)&wvh, g_wvh); cudaGetSymbolAddress((void**)&wvl, g_wvl);
    cudaGetSymbolAddress((void**)&woh, g_woh); cudaGetSymbolAddress((void**)&wol, g_wol);
    cudaGetSymbolAddress((void**)&qph, g_qph); cudaGetSymbolAddress((void**)&qpl, g_qpl);
    cudaGetSymbolAddress((void**)&kph, g_kph); cudaGetSymbolAddress((void**)&kpl, g_kpl);
    cudaGetSymbolAddress((void**)&vth, g_vth); cudaGetSymbolAddress((void**)&vtl, g_vtl);
    cudaGetSymbolAddress((void**)&ah,  g_ah);  cudaGetSymbolAddress((void**)&al,  g_al);
    cudaGetSymbolAddress((void**)&cth, g_cth); cudaGetSymbolAddress((void**)&ctl, g_ctl);
    cudaGetSymbolAddress((void**)&vp,  g_vp);

    cudaFuncSetAttribute(gemm_nt_mma, cudaFuncAttributeMaxDynamicSharedMemorySize,
                         SMEM_TOTAL);

    dim3 blk(256);
    dim3 blkG(NTHR);

    // (1) input splits, (2) weight transpose-splits
    split3_kernel<<<2048, blk>>>(q, k, v, qh, ql, kh, kl, vh, vl, MTOT * DD);
    wt4_kernel<<<dim3(8, 8, 4), dim3(32, 8)>>>(Wq, Wk, Wv, Wo,
        wqh, wql, wkh, wkl, wvh, wvl, woh, wol);

    // (3,4,5) projections
    dim3 gProj(DD / 128, MTOT / 128, 1);
    gemm_nt_mma<<<gProj, blkG, SMEM_TOTAL>>>(
        qh, ql, wqh, wql, nullptr, qph, qpl, bq,
        DD, DD, DD, 0, 0, 0, DD, /*mode=*/2, /*outPair=*/1, 1.0f);
    gemm_nt_mma<<<gProj, blkG, SMEM_TOTAL>>>(
        kh, kl, wkh, wkl, nullptr, kph, kpl, bk,
        DD, DD, DD, 0, 0, 0, DD, 2, 1, 1.0f);
    gemm_nt_mma<<<gProj, blkG, SMEM_TOTAL>>>(
        vh, vl, wvh, wvl, vp, nullptr, nullptr, bv,
        DD, DD, DD, 0, 0, 0, DD, 2, 0, 1.0f);

    // (6) causal logits
    gemm_nt_mma<<<dim3(SS / 128, SS / 128, BB), blkG, SMEM_TOTAL>>>(
        qph, qpl, kph, kpl, attn_out, nullptr, nullptr, nullptr,
        DD, DD, SS, (size_t)SS * DD, (size_t)SS * DD, (size_t)SS * SS,
        DD, /*mode=*/0, /*outPair=*/0, 0.0625f);

    // (7) Vp transpose + split
    transpose_split<<<dim3(SS / 32, DD / 32, BB), dim3(32, 8)>>>(vp, vth, vtl);

    // (8) softmax in-place + attn hi/lo pairs
    softmax_kernel<<<BB * SS, blk>>>(attn_out, ah, al);

    // (9) ctx = attn @ Vp (causal K truncation), bf16 pair output
    gemm_nt_mma<<<dim3(DD / 128, SS / 128, BB), blkG, SMEM_TOTAL>>>(
        ah, al, vth, vtl, nullptr, cth, ctl, nullptr,
        SS, SS, DD, (size_t)SS * SS, (size_t)DD * SS, (size_t)SS * DD,
        0, /*mode=*/1, /*outPair=*/1, 1.0f);

    // (10) z = ctx @ Wo + bo
    gemm_nt_mma<<<gProj, blkG, SMEM_TOTAL>>>(
        cth, ctl, woh, wol, z_out, nullptr, nullptr, bo,
        DD, DD, DD, 0, 0, 0, DD, 2, 0, 1.0f);
}

// round 15
// speedup vs baseline: 1.7307x; 1.1035x over previous
#include <cuda_runtime.h>
#include <cuda_bf16.h>
#include <math.h>
#include <stdint.h>

#define BB 4
#define SS 4096
#define DD 256
#define MTOT (BB*SS)

// ---------------------------------------------------------------------------
// Packed pair layout: bf16 array, row stride 2*Ktot elems.
// Within a row, k-chunk c (64 wide) lives at elem offset c*128: [hi 64][lo 64].
// ---------------------------------------------------------------------------
__device__ __align__(16) __nv_bfloat16 g_qP[(size_t)MTOT*2*DD];
__device__ __align__(16) __nv_bfloat16 g_kP[(size_t)MTOT*2*DD];
__device__ __align__(16) __nv_bfloat16 g_vP[(size_t)MTOT*2*DD];
__device__ __align__(16) __nv_bfloat16 g_wqP[DD*2*DD], g_wkP[DD*2*DD];
__device__ __align__(16) __nv_bfloat16 g_wvP[DD*2*DD], g_woP[DD*2*DD];
__device__ __align__(16) __nv_bfloat16 g_qpP[(size_t)MTOT*2*DD];
__device__ __align__(16) __nv_bfloat16 g_kpP[(size_t)MTOT*2*DD];
__device__ float g_vp[MTOT*DD];
__device__ __align__(16) __nv_bfloat16 g_vtP[(size_t)BB*DD*2*SS];       // Vp^T packed [b][d][2*SS]
__device__ __align__(16) __nv_bfloat16 g_aP[(size_t)BB*SS*2*SS];        // attn packed
__device__ __align__(16) __nv_bfloat16 g_ctP[(size_t)MTOT*2*DD];

// ---------------------------------------------------------------------------
// Portable-PTX helpers (compute_103-safe: sm_90 baseline features only)
// ---------------------------------------------------------------------------
__device__ __forceinline__ uint32_t smem_to_u32(const void* p) {
    uint32_t a;
    asm("{ .reg .u64 t; cvta.to.shared.u64 t, %1; cvt.u32.u64 %0, t; }" : "=r"(a) : "l"(p));
    return a;
}

#define MBARRIER_INIT(mbar, count) \
    asm volatile("mbarrier.init.shared.b64 [%0], %1;" :: "r"((uint32_t)(mbar)), "r"((uint32_t)(count)) : "memory")
#define MBARRIER_EXPECT_TX(mbar, tx) \
    asm volatile("mbarrier.arrive.expect_tx.shared.b64 _, [%0], %1;" :: "r"((uint32_t)(mbar)), "r"((uint32_t)(tx)) : "memory")
#define FENCE_PROXY_ASYNC_SHARED_CTA() asm volatile("fence.proxy.async.shared::cta;" ::: "memory")

#define MBARRIER_WAIT_PARITY(mbar_smem_addr, phase_parity) do { \
    uint32_t _mbar = (uint32_t)(mbar_smem_addr); \
    uint32_t _parity = (uint32_t)(phase_parity); \
    uint32_t _done; \
    asm volatile( \
        "{\n\t.reg .pred p;\n\t" \
        "mbarrier.try_wait.parity.acquire.cta.shared::cta.b64 p, [%1], %2;\n\t" \
        "selp.b32 %0, 1, 0, p;\n\t}" \
        : "=r"(_done) : "r"(_mbar), "r"(_parity) : "memory"); \
    if (!_done) { \
        asm volatile( \
            "{\n\t.reg .pred P1;\n\t" \
            "WAIT_LOOP_%=:\n\t" \
            "mbarrier.try_wait.parity.acquire.cta.shared::cta.b64 P1, [%0], %1, 0x989680;\n\t" \
            "@P1 bra.uni WAIT_DONE_%=;\n\t" \
            "bra.uni WAIT_LOOP_%=;\n\t" \
            "WAIT_DONE_%=:\n\t}" \
            :: "r"(_mbar), "r"(_parity) : "memory"); \
    } \
} while(0)

// 1D TMA bulk: 256B per row (hi64 + lo64 bf16), completes on mbarrier tx.
#define BULK256(dst, src, mbar) \
    asm volatile("cp.async.bulk.shared::cta.global.mbarrier::complete_tx::bytes [%0], [%1], 256, [%2];" \
        :: "r"((uint32_t)(dst)), "l"(src), "r"((uint32_t)(mbar)) : "memory")

#define LDSM4(r, addr) \
    asm volatile("ldmatrix.sync.aligned.m8n8.x4.shared.b16 {%0,%1,%2,%3}, [%4];" \
        : "=r"((r)[0]), "=r"((r)[1]), "=r"((r)[2]), "=r"((r)[3]) : "r"(addr))

#define MMA16816(d, a, b) \
    asm volatile("mma.sync.aligned.m16n8k16.row.col.f32.bf16.bf16.f32 " \
        "{%0,%1,%2,%3}, {%4,%5,%6,%7}, {%8,%9}, {%0,%1,%2,%3};" \
        : "+f"((d)[0]), "+f"((d)[1]), "+f"((d)[2]), "+f"((d)[3]) \
        : "r"((a)[0]), "r"((a)[1]), "r"((a)[2]), "r"((a)[3]), \
          "r"((b)[0]), "r"((b)[1]))

// SMEM: per row 256B (hi|lo) + 16B pad -> pitch 272B (conflict-free: 16r mod 128)
#define TPITCH 272
#define TILE_B 34816            // 128 * 272  (one operand tile: hi+lo)
#define BUF_B  (2 * TILE_B)     // A tile + B tile = 69632
#define SMEM_TOTAL (128 + 2 * BUF_B)   // mbars + double buffer = 139392
#define CHUNK_BYTES (2 * 128 * 256)    // 64 KB per chunk (A+B, hi+lo)

#define NTHR 512                // 16 warps: 4(M) x 4(N), 32x32 warp tiles

// ---------------------------------------------------------------------------
// Generic NT pair-GEMM on mma.sync bf16 (3-term hi/lo, fp32 accum):
//   C[m,n] = scale * sum_k A[m,k]*B[n,k]  (+ bias[n])
// A, B in packed-pair layout with shared ktot. mode/outPair as before.
// ---------------------------------------------------------------------------
__device__ __forceinline__ void stage_chunk(
    uint32_t buf, const __nv_bfloat16* pA, const __nv_bfloat16* pB,
    size_t rowStride, int c, uint32_t mbar, int tid)
{
    if (tid == 0) MBARRIER_EXPECT_TX(mbar, CHUNK_BYTES);
    if (tid < 256) {
        const int tile = tid >> 7, row = tid & 127;
        const __nv_bfloat16* src =
            (tile ? pB : pA) + (size_t)row * rowStride + (size_t)c * 128;
        BULK256(buf + tile * TILE_B + row * TPITCH, src, mbar);
    }
}

__global__ __launch_bounds__(NTHR) void gemm_nt_mma(
    const __nv_bfloat16* __restrict__ Ap, const __nv_bfloat16* __restrict__ Bp,
    float* __restrict__ C, __nv_bfloat16* __restrict__ Cp,
    const float* __restrict__ bias,
    int ktot, int ldc,
    size_t aBatch, size_t bBatch, size_t cBatch,
    int kFixed, int mode, int outPair, float scale)
{
    const int mBase = blockIdx.y * 128;
    const int nBase = blockIdx.x * 128;
    if (mode == 0 && nBase > mBase) return;        // fully masked logits tile
    const int b = blockIdx.z;
    const int kLen = (mode == 1) ? (mBase + 128) : kFixed;
    const int nChunks = kLen >> 6;
    const size_t rowStride = (size_t)2 * ktot;

    const __nv_bfloat16* pA = Ap + (size_t)b * aBatch + (size_t)mBase * rowStride;
    const __nv_bfloat16* pB = Bp + (size_t)b * bBatch + (size_t)nBase * rowStride;

    extern __shared__ char smem[];
    const uint32_t sb = smem_to_u32(smem);
    const uint32_t mb0 = sb, mb1 = sb + 8;
    const uint32_t bufs = sb + 128;
    const int tid = threadIdx.x;
    const int lane = tid & 31, wid = tid >> 5;
    const int warp_m = (wid & 3) * 32;             // 4 warps along M
    const int warp_n = (wid >> 2) * 32;            // 4 warps along N

    if (tid == 0) {
        MBARRIER_INIT(mb0, 1);
        MBARRIER_INIT(mb1, 1);
        FENCE_PROXY_ASYNC_SHARED_CTA();
    }
    __syncthreads();

    const uint32_t aRowOff =
        (uint32_t)(warp_m + (lane & 15)) * TPITCH + (lane >> 4) * 16;
    const uint32_t bRowOff =
        (uint32_t)(warp_n + (lane & 7) + ((lane >> 4) & 1) * 8) * TPITCH
        + ((lane >> 3) & 1) * 16;

    float acc[2][4][4];
    #pragma unroll
    for (int i = 0; i < 2; i++)
        #pragma unroll
        for (int j = 0; j < 4; j++)
            #pragma unroll
            for (int t = 0; t < 4; t++) acc[i][j][t] = 0.f;

    // prefetch chunk 0 into stage 0
    stage_chunk(bufs, pA, pB, rowStride, 0, mb0, tid);

    for (int c = 0; c < nChunks; c++) {
        if (c + 1 < nChunks)
            stage_chunk(bufs + ((c + 1) & 1) * BUF_B, pA, pB, rowStride, c + 1,
                        ((c + 1) & 1) ? mb1 : mb0, tid);
        MBARRIER_WAIT_PARITY((c & 1) ? mb1 : mb0, (c >> 1) & 1);

        const uint32_t s0 = bufs + (c & 1) * BUF_B;
        #pragma unroll
        for (int kk = 0; kk < 4; kk++) {
            uint32_t arh[2][4], arl[2][4], brh[2][4], brl[2][4];
            const uint32_t kko = kk * 32;
            #pragma unroll
            for (int mi = 0; mi < 2; mi++) {
                LDSM4(arh[mi], s0 + aRowOff + mi * (16 * TPITCH) + kko);
                LDSM4(arl[mi], s0 + aRowOff + mi * (16 * TPITCH) + kko + 128);
            }
            #pragma unroll
            for (int g = 0; g < 2; g++) {
                LDSM4(brh[g], s0 + TILE_B + bRowOff + g * (16 * TPITCH) + kko);
                LDSM4(brl[g], s0 + TILE_B + bRowOff + g * (16 * TPITCH) + kko + 128);
            }
            #pragma unroll
            for (int mi = 0; mi < 2; mi++)
                #pragma unroll
                for (int g = 0; g < 2; g++)
                    #pragma unroll
                    for (int h = 0; h < 2; h++) {
                        const int nj = g * 2 + h;
                        MMA16816(acc[mi][nj], arh[mi], &brh[g][h * 2]);
                        MMA16816(acc[mi][nj], arh[mi], &brl[g][h * 2]);
                        MMA16816(acc[mi][nj], arl[mi], &brh[g][h * 2]);
                    }
        }
        __syncthreads();   // all reads of this stage done before its refill
    }

    // Epilogue
    const int mrow = mBase + warp_m + (lane >> 2);
    const int ncol = nBase + warp_n + (lane & 3) * 2;
    float bv[4][2];
    #pragma unroll
    for (int nj = 0; nj < 4; nj++) {
        bv[nj][0] = bias ? bias[ncol + nj * 8]     : 0.f;
        bv[nj][1] = bias ? bias[ncol + nj * 8 + 1] : 0.f;
    }

    if (outPair == 0) {
        float* Cb = C + (size_t)b * cBatch;
        #pragma unroll
        for (int mi = 0; mi < 2; mi++)
            #pragma unroll
            for (int nj = 0; nj < 4; nj++) {
                const int m0 = mrow + mi * 16;
                const int n0 = ncol + nj * 8;
                float2 v0 = {acc[mi][nj][0] * scale + bv[nj][0],
                             acc[mi][nj][1] * scale + bv[nj][1]};
                float2 v1 = {acc[mi][nj][2] * scale + bv[nj][0],
                             acc[mi][nj][3] * scale + bv[nj][1]};
                *(float2*)&Cb[(size_t)m0 * ldc + n0] = v0;
                *(float2*)&Cb[(size_t)(m0 + 8) * ldc + n0] = v1;
            }
    } else {
        __nv_bfloat16* Cpb = Cp + (size_t)b * cBatch;
        const size_t ors = (size_t)2 * ldc;     // packed out row stride
        #pragma unroll
        for (int mi = 0; mi < 2; mi++)
            #pragma unroll
            for (int nj = 0; nj < 4; nj++) {
                const int m0 = mrow + mi * 16;
                const int n0 = ncol + nj * 8;
                const size_t co = (size_t)((n0 >> 6) * 128) + (n0 & 63);
                #pragma unroll
                for (int half = 0; half < 2; half++) {
                    const int m = m0 + half * 8;
                    float x0 = acc[mi][nj][half * 2 + 0] * scale + bv[nj][0];
                    float x1 = acc[mi][nj][half * 2 + 1] * scale + bv[nj][1];
                    __nv_bfloat16 h0 = __float2bfloat16(x0);
                    __nv_bfloat16 h1 = __float2bfloat16(x1);
                    __nv_bfloat162 hh; hh.x = h0; hh.y = h1;
                    __nv_bfloat162 ll;
                    ll.x = __float2bfloat16(x0 - __bfloat162float(h0));
                    ll.y = __float2bfloat16(x1 - __bfloat162float(h1));
                    *(__nv_bfloat162*)&Cpb[(size_t)m * ors + co] = hh;
                    *(__nv_bfloat162*)&Cpb[(size_t)m * ors + co + 64] = ll;
                }
            }
    }
}

// ---------------------------------------------------------------------------
// Fused fp32 -> packed hi/lo split for q, k, v (Ktot = DD)
// ---------------------------------------------------------------------------
__global__ __launch_bounds__(256) void split3_kernel(
    const float* __restrict__ q, const float* __restrict__ k, const float* __restrict__ v,
    __nv_bfloat16* __restrict__ qP, __nv_bfloat16* __restrict__ kP,
    __nv_bfloat16* __restrict__ vP, int n)
{
    for (int i = blockIdx.x * blockDim.x + threadIdx.x; i < n; i += gridDim.x * blockDim.x) {
        const int row = i >> 8, kk = i & 255;
        const size_t off = (size_t)row * 512 + ((kk >> 6) * 128) + (kk & 63);
        float a = q[i], b = k[i], c = v[i];
        __nv_bfloat16 ha = __float2bfloat16(a);
        __nv_bfloat16 hb = __float2bfloat16(b);
        __nv_bfloat16 hc = __float2bfloat16(c);
        qP[off] = ha; qP[off + 64] = __float2bfloat16(a - __bfloat162float(ha));
        kP[off] = hb; kP[off + 64] = __float2bfloat16(b - __bfloat162float(hb));
        vP[off] = hc; vP[off + 64] = __float2bfloat16(c - __bfloat162float(hc));
    }
}

// ---------------------------------------------------------------------------
// All four W[k][n] -> packed Wt [n][2*DD] transpose-splits (z selects)
// ---------------------------------------------------------------------------
__global__ void wt4_kernel(
    const float* __restrict__ Wq, const float* __restrict__ Wk,
    const float* __restrict__ Wv, const float* __restrict__ Wo,
    __nv_bfloat16* __restrict__ qP, __nv_bfloat16* __restrict__ kP,
    __nv_bfloat16* __restrict__ vP, __nv_bfloat16* __restrict__ oP)
{
    const float* W;
    __nv_bfloat16* tP;
    switch (blockIdx.z) {
        case 0:  W = Wq; tP = qP; break;
        case 1:  W = Wk; tP = kP; break;
        case 2:  W = Wv; tP = vP; break;
        default: W = Wo; tP = oP; break;
    }
    __shared__ float t[32][33];
    const int k0 = blockIdx.x * 32, n0 = blockIdx.y * 32;
    #pragma unroll
    for (int i = 0; i < 32; i += 8)
        t[threadIdx.y + i][threadIdx.x] = W[(size_t)(k0 + threadIdx.y + i) * DD + n0 + threadIdx.x];
    __syncthreads();
    #pragma unroll
    for (int i = 0; i < 32; i += 8) {
        float x = t[threadIdx.x][threadIdx.y + i];
        __nv_bfloat16 hh = __float2bfloat16(x);
        const int kk = k0 + threadIdx.x;
        size_t o = (size_t)(n0 + threadIdx.y + i) * 512 + ((kk >> 6) * 128) + (kk & 63);
        tP[o] = hh;
        tP[o + 64] = __float2bfloat16(x - __bfloat162float(hh));
    }
}

// ---------------------------------------------------------------------------
// Vp [b][s][d] -> packed Vp^T [b][d][2*SS]
// ---------------------------------------------------------------------------
__global__ __launch_bounds__(256) void transpose_split(
    const float* __restrict__ V, __nv_bfloat16* __restrict__ vtP)
{
    __shared__ float t[32][33];
    const int b = blockIdx.z;
    const int s0 = blockIdx.x * 32, d0 = blockIdx.y * 32;
    const float* Vb = V + (size_t)b * SS * DD;
    #pragma unroll
    for (int i = 0; i < 32; i += 8)
        t[threadIdx.y + i][threadIdx.x] = Vb[(size_t)(s0 + threadIdx.y + i) * DD + d0 + threadIdx.x];
    __syncthreads();
    #pragma unroll
    for (int i = 0; i < 32; i += 8) {
        float x = t[threadIdx.x][threadIdx.y + i];
        __nv_bfloat16 hh = __float2bfloat16(x);
        const int s = s0 + threadIdx.x;
        size_t o = ((size_t)b * DD + (d0 + threadIdx.y + i)) * (2 * SS)
                 + ((s >> 6) * 128) + (s & 63);
        vtP[o] = hh;
        vtP[o + 64] = __float2bfloat16(x - __bfloat162float(hh));
    }
}

// ---------------------------------------------------------------------------
// Row softmax in-place + packed attn hi/lo (only to diagonal-tile edge).
// ---------------------------------------------------------------------------
__global__ __launch_bounds__(256) void softmax_kernel(
    float* __restrict__ attn, __nv_bfloat16* __restrict__ aP)
{
    __shared__ float row[SS];
    __shared__ float red[256];
    const int gid = blockIdx.x;          // b*SS + q
    const int q = gid % SS;
    float* r = attn + (size_t)gid * SS;
    __nv_bfloat16* arow = aP + (size_t)gid * (2 * SS);
    const int n = q + 1;
    const int kcap = ((q >> 7) + 1) << 7;   // ceil((q+1)/128)*128
    const int tid = threadIdx.x;

    float mx = -1e30f;
    for (int k = tid; k < n; k += 256) {
        float v = r[k];
        row[k] = v;
        mx = fmaxf(mx, v);
    }
    red[tid] = mx;
    __syncthreads();
    #pragma unroll
    for (int s = 128; s > 0; s >>= 1) {
        if (tid < s) red[tid] = fmaxf(red[tid], red[tid + s]);
        __syncthreads();
    }
    const float mxv = red[0];
    __syncthreads();

    float sum = 0.f;
    for (int k = tid; k < n; k += 256) {
        float e = expf(row[k] - mxv);
        row[k] = e;
        sum += e;
    }
    red[tid] = sum;
    __syncthreads();
    #pragma unroll
    for (int s = 128; s > 0; s >>= 1) {
        if (tid < s) red[tid] += red[tid + s];
        __syncthreads();
    }
    const float inv = 1.0f / red[0];

    for (int k = tid; k < n; k += 256) {
        float p = row[k] * inv;
        r[k] = p;
        const size_t off = (size_t)((k >> 6) * 128) + (k & 63);
        __nv_bfloat16 h = __float2bfloat16(p);
        arow[off] = h;
        arow[off + 64] = __float2bfloat16(p - __bfloat162float(h));
    }
    const __nv_bfloat16 z = __float2bfloat16(0.0f);
    for (int k = n + tid; k < kcap; k += 256) {
        const size_t off = (size_t)((k >> 6) * 128) + (k & 63);
        arow[off] = z;
        arow[off + 64] = z;
    }
    for (int k = n + tid; k < SS; k += 256) r[k] = 0.0f;  // fp32 output: full
}

// ---------------------------------------------------------------------------
extern "C" void kernel_launch(void* const* d_in, const int* in_sizes, int n_in,
                              void* d_out, int out_size)
{
    const float* q  = (const float*)d_in[0];
    const float* k  = (const float*)d_in[1];
    const float* v  = (const float*)d_in[2];
    // d_in[3] = mask (deterministic causal triu; handled analytically)
    const float* Wq = (const float*)d_in[4];
    const float* bq = (const float*)d_in[5];
    const float* Wk = (const float*)d_in[6];
    const float* bk = (const float*)d_in[7];
    const float* Wv = (const float*)d_in[8];
    const float* bv = (const float*)d_in[9];
    const float* Wo = (const float*)d_in[10];
    const float* bo = (const float*)d_in[11];

    float* z_out    = (float*)d_out;
    float* attn_out = z_out + (size_t)BB * SS * DD;

    __nv_bfloat16 *qP, *kP, *vP, *wqP, *wkP, *wvP, *woP;
    __nv_bfloat16 *qpP, *kpP, *vtP, *aP, *ctP;
    float* vp;
    cudaGetSymbolAddress((void**)&qP,  g_qP);
    cudaGetSymbolAddress((void**)&kP,  g_kP);
    cudaGetSymbolAddress((void**)&vP,  g_vP);
    cudaGetSymbolAddress((void**)&wqP, g_wqP);
    cudaGetSymbolAddress((void**)&wkP, g_wkP);
    cudaGetSymbolAddress((void**)&wvP, g_wvP);
    cudaGetSymbolAddress((void**)&woP, g_woP);
    cudaGetSymbolAddress((void**)&qpP, g_qpP);
    cudaGetSymbolAddress((void**)&kpP, g_kpP);
    cudaGetSymbolAddress((void**)&vtP, g_vtP);
    cudaGetSymbolAddress((void**)&aP,  g_aP);
    cudaGetSymbolAddress((void**)&ctP, g_ctP);
    cudaGetSymbolAddress((void**)&vp,  g_vp);

    cudaFuncSetAttribute(gemm_nt_mma, cudaFuncAttributeMaxDynamicSharedMemorySize,
                         SMEM_TOTAL);

    dim3 blk(256);
    dim3 blkG(NTHR);

    // (1) input splits, (2) weight transpose-splits (both packed)
    split3_kernel<<<2048, blk>>>(q, k, v, qP, kP, vP, MTOT * DD);
    wt4_kernel<<<dim3(8, 8, 4), dim3(32, 8)>>>(Wq, Wk, Wv, Wo, wqP, wkP, wvP, woP);

    // (3,4,5) projections
    dim3 gProj(DD / 128, MTOT / 128, 1);
    gemm_nt_mma<<<gProj, blkG, SMEM_TOTAL>>>(
        qP, wqP, nullptr, qpP, bq,
        DD, DD, 0, 0, 0, DD, /*mode=*/2, /*outPair=*/1, 1.0f);
    gemm_nt_mma<<<gProj, blkG, SMEM_TOTAL>>>(
        kP, wkP, nullptr, kpP, bk,
        DD, DD, 0, 0, 0, DD, 2, 1, 1.0f);
    gemm_nt_mma<<<gProj, blkG, SMEM_TOTAL>>>(
        vP, wvP, vp, nullptr, bv,
        DD, DD, 0, 0, 0, DD, 2, 0, 1.0f);

    // (6) causal logits (fp32 into attn region of d_out)
    gemm_nt_mma<<<dim3(SS / 128, SS / 128, BB), blkG, SMEM_TOTAL>>>(
        qpP, kpP, attn_out, nullptr, nullptr,
        DD, SS, (size_t)SS * 2 * DD, (size_t)SS * 2 * DD, (size_t)SS * SS,
        DD, /*mode=*/0, /*outPair=*/0, 0.0625f);

    // (7) Vp transpose + packed split
    transpose_split<<<dim3(SS / 32, DD / 32, BB), dim3(32, 8)>>>(vp, vtP);

    // (8) softmax in-place + packed attn pairs
    softmax_kernel<<<BB * SS, blk>>>(attn_out, aP);

    // (9) ctx = attn @ Vp (causal K truncation), packed pair output
    gemm_nt_mma<<<dim3(DD / 128, SS / 128, BB), blkG, SMEM_TOTAL>>>(
        aP, vtP, nullptr, ctP, nullptr,
        SS, DD, (size_t)SS * 2 * SS, (size_t)DD * 2 * SS, (size_t)SS * 2 * DD,
        0, /*mode=*/1, /*outPair=*/1, 1.0f);

    // (10) z = ctx @ Wo + bo (fp32 into d_out)
    gemm_nt_mma<<<gProj, blkG, SMEM_TOTAL>>>(
        ctP, woP, z_out, nullptr, bo,
        DD, DD, 0, 0, (size_t)SS * DD, DD, 2, 0, 1.0f);
}

// round 17
// speedup vs baseline: 1.7309x; 1.0001x over previous
#include <cuda_runtime.h>
#include <cuda_bf16.h>
#include <math.h>
#include <stdint.h>

#define BB 4
#define SS 4096
#define DD 256
#define MTOT (BB*SS)

// ---------------------------------------------------------------------------
// Packed pair layout: bf16 array, row stride 2*Ktot elems.
// Within a row, k-chunk c (64 wide) lives at elem offset c*128: [hi 64][lo 64].
// ---------------------------------------------------------------------------
__device__ __align__(16) __nv_bfloat16 g_qP[(size_t)MTOT*2*DD];
__device__ __align__(16) __nv_bfloat16 g_kP[(size_t)MTOT*2*DD];
__device__ __align__(16) __nv_bfloat16 g_vP[(size_t)MTOT*2*DD];
__device__ __align__(16) __nv_bfloat16 g_wqP[DD*2*DD], g_wkP[DD*2*DD];
__device__ __align__(16) __nv_bfloat16 g_wvP[DD*2*DD], g_woP[DD*2*DD];
__device__ __align__(16) __nv_bfloat16 g_qpP[(size_t)MTOT*2*DD];
__device__ __align__(16) __nv_bfloat16 g_kpP[(size_t)MTOT*2*DD];
__device__ float g_vp[MTOT*DD];
__device__ __align__(16) __nv_bfloat16 g_vtP[(size_t)BB*DD*2*SS];       // Vp^T packed [b][d][2*SS]
__device__ __align__(16) __nv_bfloat16 g_aP[(size_t)BB*SS*2*SS];        // attn packed
__device__ __align__(16) __nv_bfloat16 g_ctP[(size_t)MTOT*2*DD];

// ---------------------------------------------------------------------------
// Portable-PTX helpers (compute_103-safe: sm_90 baseline features only)
// ---------------------------------------------------------------------------
__device__ __forceinline__ uint32_t smem_to_u32(const void* p) {
    uint32_t a;
    asm("{ .reg .u64 t; cvta.to.shared.u64 t, %1; cvt.u32.u64 %0, t; }" : "=r"(a) : "l"(p));
    return a;
}

#define MBARRIER_INIT(mbar, count) \
    asm volatile("mbarrier.init.shared.b64 [%0], %1;" :: "r"((uint32_t)(mbar)), "r"((uint32_t)(count)) : "memory")
#define MBARRIER_EXPECT_TX(mbar, tx) \
    asm volatile("mbarrier.arrive.expect_tx.shared.b64 _, [%0], %1;" :: "r"((uint32_t)(mbar)), "r"((uint32_t)(tx)) : "memory")
#define FENCE_PROXY_ASYNC_SHARED_CTA() asm volatile("fence.proxy.async.shared::cta;" ::: "memory")

#define MBARRIER_WAIT_PARITY(mbar_smem_addr, phase_parity) do { \
    uint32_t _mbar = (uint32_t)(mbar_smem_addr); \
    uint32_t _parity = (uint32_t)(phase_parity); \
    uint32_t _done; \
    asm volatile( \
        "{\n\t.reg .pred p;\n\t" \
        "mbarrier.try_wait.parity.acquire.cta.shared::cta.b64 p, [%1], %2;\n\t" \
        "selp.b32 %0, 1, 0, p;\n\t}" \
        : "=r"(_done) : "r"(_mbar), "r"(_parity) : "memory"); \
    if (!_done) { \
        asm volatile( \
            "{\n\t.reg .pred P1;\n\t" \
            "WAIT_LOOP_%=:\n\t" \
            "mbarrier.try_wait.parity.acquire.cta.shared::cta.b64 P1, [%0], %1, 0x989680;\n\t" \
            "@P1 bra.uni WAIT_DONE_%=;\n\t" \
            "bra.uni WAIT_LOOP_%=;\n\t" \
            "WAIT_DONE_%=:\n\t}" \
            :: "r"(_mbar), "r"(_parity) : "memory"); \
    } \
} while(0)

// 1D TMA bulk: 256B per row (hi64 + lo64 bf16), completes on mbarrier tx.
#define BULK256(dst, src, mbar) \
    asm volatile("cp.async.bulk.shared::cta.global.mbarrier::complete_tx::bytes [%0], [%1], 256, [%2];" \
        :: "r"((uint32_t)(dst)), "l"(src), "r"((uint32_t)(mbar)) : "memory")

#define LDSM4(r, addr) \
    asm volatile("ldmatrix.sync.aligned.m8n8.x4.shared.b16 {%0,%1,%2,%3}, [%4];" \
        : "=r"((r)[0]), "=r"((r)[1]), "=r"((r)[2]), "=r"((r)[3]) : "r"(addr))

#define MMA16816(d, a, b) \
    asm volatile("mma.sync.aligned.m16n8k16.row.col.f32.bf16.bf16.f32 " \
        "{%0,%1,%2,%3}, {%4,%5,%6,%7}, {%8,%9}, {%0,%1,%2,%3};" \
        : "+f"((d)[0]), "+f"((d)[1]), "+f"((d)[2]), "+f"((d)[3]) \
        : "r"((a)[0]), "r"((a)[1]), "r"((a)[2]), "r"((a)[3]), \
          "r"((b)[0]), "r"((b)[1]))

// SMEM: per row 256B (hi|lo) + 16B pad -> pitch 272B (conflict-free: 16r mod 128)
#define TPITCH 272
#define TILE_B 34816            // 128 * 272  (one operand tile: hi+lo)
#define BUF_B  (2 * TILE_B)     // A tile + B tile = 69632
#define NSTAGE 3
#define SMEM_TOTAL (128 + NSTAGE * BUF_B)   // mbars + 3-stage = 209024
#define CHUNK_BYTES (2 * 128 * 256)         // 64 KB per chunk (A+B, hi+lo)

#define NTHR 512                // 16 warps: 4(M) x 4(N), 32x32 warp tiles

// ---------------------------------------------------------------------------
// Generic NT pair-GEMM on mma.sync bf16 (3-term hi/lo, fp32 accum):
//   C[m,n] = scale * sum_k A[m,k]*B[n,k]  (+ bias[n])
// A, B in packed-pair layout with shared ktot. mode/outPair as before.
// ---------------------------------------------------------------------------
__device__ __forceinline__ void stage_chunk(
    uint32_t buf, const __nv_bfloat16* pA, const __nv_bfloat16* pB,
    size_t rowStride, int c, uint32_t mbar, int tid)
{
    if (tid == 0) MBARRIER_EXPECT_TX(mbar, CHUNK_BYTES);
    if (tid < 256) {
        const int tile = tid >> 7, row = tid & 127;
        const __nv_bfloat16* src =
            (tile ? pB : pA) + (size_t)row * rowStride + (size_t)c * 128;
        BULK256(buf + tile * TILE_B + row * TPITCH, src, mbar);
    }
}

__device__ __forceinline__ void load_frags(
    uint32_t s0, uint32_t aRowOff, uint32_t bRowOff, int kk,
    uint32_t arh[2][4], uint32_t arl[2][4],
    uint32_t brh[2][4], uint32_t brl[2][4])
{
    const uint32_t kko = kk * 32;
    #pragma unroll
    for (int mi = 0; mi < 2; mi++) {
        LDSM4(arh[mi], s0 + aRowOff + mi * (16 * TPITCH) + kko);
        LDSM4(arl[mi], s0 + aRowOff + mi * (16 * TPITCH) + kko + 128);
    }
    #pragma unroll
    for (int g = 0; g < 2; g++) {
        LDSM4(brh[g], s0 + TILE_B + bRowOff + g * (16 * TPITCH) + kko);
        LDSM4(brl[g], s0 + TILE_B + bRowOff + g * (16 * TPITCH) + kko + 128);
    }
}

__global__ __launch_bounds__(NTHR) void gemm_nt_mma(
    const __nv_bfloat16* __restrict__ Ap, const __nv_bfloat16* __restrict__ Bp,
    float* __restrict__ C, __nv_bfloat16* __restrict__ Cp,
    const float* __restrict__ bias,
    int ktot, int ldc,
    size_t aBatch, size_t bBatch, size_t cBatch,
    int kFixed, int mode, int outPair, float scale)
{
    // mode 1 (ctx): reverse M order so heaviest (largest-K) CTAs start first.
    const int mIdx = (mode == 1) ? (gridDim.y - 1 - blockIdx.y) : blockIdx.y;
    const int mBase = mIdx * 128;
    const int nBase = blockIdx.x * 128;
    if (mode == 0 && nBase > mBase) return;        // fully masked logits tile
    const int b = blockIdx.z;
    const int kLen = (mode == 1) ? (mBase + 128) : kFixed;
    const int nChunks = kLen >> 6;
    const size_t rowStride = (size_t)2 * ktot;

    const __nv_bfloat16* pA = Ap + (size_t)b * aBatch + (size_t)mBase * rowStride;
    const __nv_bfloat16* pB = Bp + (size_t)b * bBatch + (size_t)nBase * rowStride;

    extern __shared__ char smem[];
    const uint32_t sb = smem_to_u32(smem);
    const uint32_t bufs = sb + 128;
    const int tid = threadIdx.x;
    const int lane = tid & 31, wid = tid >> 5;
    const int warp_m = (wid & 3) * 32;             // 4 warps along M
    const int warp_n = (wid >> 2) * 32;            // 4 warps along N

    if (tid == 0) {
        MBARRIER_INIT(sb + 0,  1);
        MBARRIER_INIT(sb + 8,  1);
        MBARRIER_INIT(sb + 16, 1);
        FENCE_PROXY_ASYNC_SHARED_CTA();
    }
    __syncthreads();

    const uint32_t aRowOff =
        (uint32_t)(warp_m + (lane & 15)) * TPITCH + (lane >> 4) * 16;
    const uint32_t bRowOff =
        (uint32_t)(warp_n + (lane & 7) + ((lane >> 4) & 1) * 8) * TPITCH
        + ((lane >> 3) & 1) * 16;

    float acc[2][4][4];
    #pragma unroll
    for (int i = 0; i < 2; i++)
        #pragma unroll
        for (int j = 0; j < 4; j++)
            #pragma unroll
            for (int t = 0; t < 4; t++) acc[i][j][t] = 0.f;

    // prefetch chunks 0,1 into stages 0,1
    stage_chunk(bufs, pA, pB, rowStride, 0, sb + 0, tid);
    if (nChunks > 1)
        stage_chunk(bufs + BUF_B, pA, pB, rowStride, 1, sb + 8, tid);

    for (int c = 0; c < nChunks; c++) {
        const int st = c % NSTAGE;
        if (c + 2 < nChunks) {
            const int st2 = (c + 2) % NSTAGE;
            stage_chunk(bufs + st2 * BUF_B, pA, pB, rowStride, c + 2,
                        sb + st2 * 8, tid);
        }
        MBARRIER_WAIT_PARITY(sb + st * 8, (c / NSTAGE) & 1);

        const uint32_t s0 = bufs + st * BUF_B;
        uint32_t arh[2][2][4], arl[2][2][4], brh[2][2][4], brl[2][2][4];
        load_frags(s0, aRowOff, bRowOff, 0, arh[0], arl[0], brh[0], brl[0]);
        #pragma unroll
        for (int kk = 0; kk < 4; kk++) {
            const int cur = kk & 1;
            if (kk < 3)
                load_frags(s0, aRowOff, bRowOff, kk + 1,
                           arh[cur ^ 1], arl[cur ^ 1], brh[cur ^ 1], brl[cur ^ 1]);
            #pragma unroll
            for (int mi = 0; mi < 2; mi++)
                #pragma unroll
                for (int g = 0; g < 2; g++)
                    #pragma unroll
                    for (int h = 0; h < 2; h++) {
                        const int nj = g * 2 + h;
                        MMA16816(acc[mi][nj], arh[cur][mi], &brh[cur][g][h * 2]);
                        MMA16816(acc[mi][nj], arh[cur][mi], &brl[cur][g][h * 2]);
                        MMA16816(acc[mi][nj], arl[cur][mi], &brh[cur][g][h * 2]);
                    }
        }
        __syncthreads();   // all reads of this stage done before its refill
    }

    // Epilogue
    const int mrow = mBase + warp_m + (lane >> 2);
    const int ncol = nBase + warp_n + (lane & 3) * 2;
    float bv[4][2];
    #pragma unroll
    for (int nj = 0; nj < 4; nj++) {
        bv[nj][0] = bias ? bias[ncol + nj * 8]     : 0.f;
        bv[nj][1] = bias ? bias[ncol + nj * 8 + 1] : 0.f;
    }

    if (outPair == 0) {
        float* Cb = C + (size_t)b * cBatch;
        #pragma unroll
        for (int mi = 0; mi < 2; mi++)
            #pragma unroll
            for (int nj = 0; nj < 4; nj++) {
                const int m0 = mrow + mi * 16;
                const int n0 = ncol + nj * 8;
                float2 v0 = {acc[mi][nj][0] * scale + bv[nj][0],
                             acc[mi][nj][1] * scale + bv[nj][1]};
                float2 v1 = {acc[mi][nj][2] * scale + bv[nj][0],
                             acc[mi][nj][3] * scale + bv[nj][1]};
                *(float2*)&Cb[(size_t)m0 * ldc + n0] = v0;
                *(float2*)&Cb[(size_t)(m0 + 8) * ldc + n0] = v1;
            }
    } else {
        __nv_bfloat16* Cpb = Cp + (size_t)b * cBatch;
        const size_t ors = (size_t)2 * ldc;     // packed out row stride
        #pragma unroll
        for (int mi = 0; mi < 2; mi++)
            #pragma unroll
            for (int nj = 0; nj < 4; nj++) {
                const int m0 = mrow + mi * 16;
                const int n0 = ncol + nj * 8;
                const size_t co = (size_t)((n0 >> 6) * 128) + (n0 & 63);
                #pragma unroll
                for (int half = 0; half < 2; half++) {
                    const int m = m0 + half * 8;
                    float x0 = acc[mi][nj][half * 2 + 0] * scale + bv[nj][0];
                    float x1 = acc[mi][nj][half * 2 + 1] * scale + bv[nj][1];
                    __nv_bfloat16 h0 = __float2bfloat16(x0);
                    __nv_bfloat16 h1 = __float2bfloat16(x1);
                    __nv_bfloat162 hh; hh.x = h0; hh.y = h1;
                    __nv_bfloat162 ll;
                    ll.x = __float2bfloat16(x0 - __bfloat162float(h0));
                    ll.y = __float2bfloat16(x1 - __bfloat162float(h1));
                    *(__nv_bfloat162*)&Cpb[(size_t)m * ors + co] = hh;
                    *(__nv_bfloat162*)&Cpb[(size_t)m * ors + co + 64] = ll;
                }
            }
    }
}

// ---------------------------------------------------------------------------
// Fused fp32 -> packed hi/lo split for q, k, v (Ktot = DD)
// ---------------------------------------------------------------------------
__global__ __launch_bounds__(256) void split3_kernel(
    const float* __restrict__ q, const float* __restrict__ k, const float* __restrict__ v,
    __nv_bfloat16* __restrict__ qP, __nv_bfloat16* __restrict__ kP,
    __nv_bfloat16* __restrict__ vP, int n)
{
    for (int i = blockIdx.x * blockDim.x + threadIdx.x; i < n; i += gridDim.x * blockDim.x) {
        const int row = i >> 8, kk = i & 255;
        const size_t off = (size_t)row * 512 + ((kk >> 6) * 128) + (kk & 63);
        float a = q[i], b = k[i], c = v[i];
        __nv_bfloat16 ha = __float2bfloat16(a);
        __nv_bfloat16 hb = __float2bfloat16(b);
        __nv_bfloat16 hc = __float2bfloat16(c);
        qP[off] = ha; qP[off + 64] = __float2bfloat16(a - __bfloat162float(ha));
        kP[off] = hb; kP[off + 64] = __float2bfloat16(b - __bfloat162float(hb));
        vP[off] = hc; vP[off + 64] = __float2bfloat16(c - __bfloat162float(hc));
    }
}

// ---------------------------------------------------------------------------
// All four W[k][n] -> packed Wt [n][2*DD] transpose-splits (z selects)
// ---------------------------------------------------------------------------
__global__ void wt4_kernel(
    const float* __restrict__ Wq, const float* __restrict__ Wk,
    const float* __restrict__ Wv, const float* __restrict__ Wo,
    __nv_bfloat16* __restrict__ qP, __nv_bfloat16* __restrict__ kP,
    __nv_bfloat16* __restrict__ vP, __nv_bfloat16* __restrict__ oP)
{
    const float* W;
    __nv_bfloat16* tP;
    switch (blockIdx.z) {
        case 0:  W = Wq; tP = qP; break;
        case 1:  W = Wk; tP = kP; break;
        case 2:  W = Wv; tP = vP; break;
        default: W = Wo; tP = oP; break;
    }
    __shared__ float t[32][33];
    const int k0 = blockIdx.x * 32, n0 = blockIdx.y * 32;
    #pragma unroll
    for (int i = 0; i < 32; i += 8)
        t[threadIdx.y + i][threadIdx.x] = W[(size_t)(k0 + threadIdx.y + i) * DD + n0 + threadIdx.x];
    __syncthreads();
    #pragma unroll
    for (int i = 0; i < 32; i += 8) {
        float x = t[threadIdx.x][threadIdx.y + i];
        __nv_bfloat16 hh = __float2bfloat16(x);
        const int kk = k0 + threadIdx.x;
        size_t o = (size_t)(n0 + threadIdx.y + i) * 512 + ((kk >> 6) * 128) + (kk & 63);
        tP[o] = hh;
        tP[o + 64] = __float2bfloat16(x - __bfloat162float(hh));
    }
}

// ---------------------------------------------------------------------------
// Vp [b][s][d] -> packed Vp^T [b][d][2*SS]
// ---------------------------------------------------------------------------
__global__ __launch_bounds__(256) void transpose_split(
    const float* __restrict__ V, __nv_bfloat16* __restrict__ vtP)
{
    __shared__ float t[32][33];
    const int b = blockIdx.z;
    const int s0 = blockIdx.x * 32, d0 = blockIdx.y * 32;
    const float* Vb = V + (size_t)b * SS * DD;
    #pragma unroll
    for (int i = 0; i < 32; i += 8)
        t[threadIdx.y + i][threadIdx.x] = Vb[(size_t)(s0 + threadIdx.y + i) * DD + d0 + threadIdx.x];
    __syncthreads();
    #pragma unroll
    for (int i = 0; i < 32; i += 8) {
        float x = t[threadIdx.x][threadIdx.y + i];
        __nv_bfloat16 hh = __float2bfloat16(x);
        const int s = s0 + threadIdx.x;
        size_t o = ((size_t)b * DD + (d0 + threadIdx.y + i)) * (2 * SS)
                 + ((s >> 6) * 128) + (s & 63);
        vtP[o] = hh;
        vtP[o + 64] = __float2bfloat16(x - __bfloat162float(hh));
    }
}

// ---------------------------------------------------------------------------
// Row softmax in-place + packed attn hi/lo (only to diagonal-tile edge).
// ---------------------------------------------------------------------------
__global__ __launch_bounds__(256) void softmax_kernel(
    float* __restrict__ attn, __nv_bfloat16* __restrict__ aP)
{
    __shared__ float row[SS];
    __shared__ float red[256];
    const int gid = blockIdx.x;          // b*SS + q
    const int q = gid % SS;
    float* r = attn + (size_t)gid * SS;
    __nv_bfloat16* arow = aP + (size_t)gid * (2 * SS);
    const int n = q + 1;
    const int kcap = ((q >> 7) + 1) << 7;   // ceil((q+1)/128)*128
    const int tid = threadIdx.x;

    float mx = -1e30f;
    for (int k = tid; k < n; k += 256) {
        float v = r[k];
        row[k] = v;
        mx = fmaxf(mx, v);
    }
    red[tid] = mx;
    __syncthreads();
    #pragma unroll
    for (int s = 128; s > 0; s >>= 1) {
        if (tid < s) red[tid] = fmaxf(red[tid], red[tid + s]);
        __syncthreads();
    }
    const float mxv = red[0];
    __syncthreads();

    float sum = 0.f;
    for (int k = tid; k < n; k += 256) {
        float e = expf(row[k] - mxv);
        row[k] = e;
        sum += e;
    }
    red[tid] = sum;
    __syncthreads();
    #pragma unroll
    for (int s = 128; s > 0; s >>= 1) {
        if (tid < s) red[tid] += red[tid + s];
        __syncthreads();
    }
    const float inv = 1.0f / red[0];

    for (int k = tid; k < n; k += 256) {
        float p = row[k] * inv;
        r[k] = p;
        const size_t off = (size_t)((k >> 6) * 128) + (k & 63);
        __nv_bfloat16 h = __float2bfloat16(p);
        arow[off] = h;
        arow[off + 64] = __float2bfloat16(p - __bfloat162float(h));
    }
    const __nv_bfloat16 z = __float2bfloat16(0.0f);
    for (int k = n + tid; k < kcap; k += 256) {
        const size_t off = (size_t)((k >> 6) * 128) + (k & 63);
        arow[off] = z;
        arow[off + 64] = z;
    }
    for (int k = n + tid; k < SS; k += 256) r[k] = 0.0f;  // fp32 output: full
}

// ---------------------------------------------------------------------------
extern "C" void kernel_launch(void* const* d_in, const int* in_sizes, int n_in,
                              void* d_out, int out_size)
{
    const float* q  = (const float*)d_in[0];
    const float* k  = (const float*)d_in[1];
    const float* v  = (const float*)d_in[2];
    // d_in[3] = mask (deterministic causal triu; handled analytically)
    const float* Wq = (const float*)d_in[4];
    const float* bq = (const float*)d_in[5];
    const float* Wk = (const float*)d_in[6];
    const float* bk = (const float*)d_in[7];
    const float* Wv = (const float*)d_in[8];
    const float* bv = (const float*)d_in[9];
    const float* Wo = (const float*)d_in[10];
    const float* bo = (const float*)d_in[11];

    float* z_out    = (float*)d_out;
    float* attn_out = z_out + (size_t)BB * SS * DD;

    __nv_bfloat16 *qP, *kP, *vP, *wqP, *wkP, *wvP, *woP;
    __nv_bfloat16 *qpP, *kpP, *vtP, *aP, *ctP;
    float* vp;
    cudaGetSymbolAddress((void**)&qP,  g_qP);
    cudaGetSymbolAddress((void**)&kP,  g_kP);
    cudaGetSymbolAddress((void**)&vP,  g_vP);
    cudaGetSymbolAddress((void**)&wqP, g_wqP);
    cudaGetSymbolAddress((void**)&wkP, g_wkP);
    cudaGetSymbolAddress((void**)&wvP, g_wvP);
    cudaGetSymbolAddress((void**)&woP, g_woP);
    cudaGetSymbolAddress((void**)&qpP, g_qpP);
    cudaGetSymbolAddress((void**)&kpP, g_kpP);
    cudaGetSymbolAddress((void**)&vtP, g_vtP);
    cudaGetSymbolAddress((void**)&aP,  g_aP);
    cudaGetSymbolAddress((void**)&ctP, g_ctP);
    cudaGetSymbolAddress((void**)&vp,  g_vp);

    cudaFuncSetAttribute(gemm_nt_mma, cudaFuncAttributeMaxDynamicSharedMemorySize,
                         SMEM_TOTAL);

    dim3 blk(256);
    dim3 blkG(NTHR);

    // (1) input splits, (2) weight transpose-splits (both packed)
    split3_kernel<<<2048, blk>>>(q, k, v, qP, kP, vP, MTOT * DD);
    wt4_kernel<<<dim3(8, 8, 4), dim3(32, 8)>>>(Wq, Wk, Wv, Wo, wqP, wkP, wvP, woP);

    // (3,4,5) projections
    dim3 gProj(DD / 128, MTOT / 128, 1);
    gemm_nt_mma<<<gProj, blkG, SMEM_TOTAL>>>(
        qP, wqP, nullptr, qpP, bq,
        DD, DD, 0, 0, 0, DD, /*mode=*/2, /*outPair=*/1, 1.0f);
    gemm_nt_mma<<<gProj, blkG, SMEM_TOTAL>>>(
        kP, wkP, nullptr, kpP, bk,
        DD, DD, 0, 0, 0, DD, 2, 1, 1.0f);
    gemm_nt_mma<<<gProj, blkG, SMEM_TOTAL>>>(
        vP, wvP, vp, nullptr, bv,
        DD, DD, 0, 0, 0, DD, 2, 0, 1.0f);

    // (6) causal logits (fp32 into attn region of d_out)
    gemm_nt_mma<<<dim3(SS / 128, SS / 128, BB), blkG, SMEM_TOTAL>>>(
        qpP, kpP, attn_out, nullptr, nullptr,
        DD, SS, (size_t)SS * 2 * DD, (size_t)SS * 2 * DD, (size_t)SS * SS,
        DD, /*mode=*/0, /*outPair=*/0, 0.0625f);

    // (7) Vp transpose + packed split
    transpose_split<<<dim3(SS / 32, DD / 32, BB), dim3(32, 8)>>>(vp, vtP);

    // (8) softmax in-place + packed attn pairs
    softmax_kernel<<<BB * SS, blk>>>(attn_out, aP);

    // (9) ctx = attn @ Vp (causal K truncation), packed pair output
    gemm_nt_mma<<<dim3(DD / 128, SS / 128, BB), blkG, SMEM_TOTAL>>>(
        aP, vtP, nullptr, ctP, nullptr,
        SS, DD, (size_t)SS * 2 * SS, (size_t)DD * 2 * SS, (size_t)SS * 2 * DD,
        0, /*mode=*/1, /*outPair=*/1, 1.0f);

    // (10) z = ctx @ Wo + bo (fp32 into d_out)
    gemm_nt_mma<<<gProj, blkG, SMEM_TOTAL>>>(
        ctP, woP, z_out, nullptr, bo,
        DD, DD, 0, 0, (size_t)SS * DD, DD, 2, 0, 1.0f);
}